// round 10
// baseline (speedup 1.0000x reference)
#include <cuda_runtime.h>
#include <cuda_fp16.h>
#include <math.h>
#include <stdint.h>

#define BATCH 256
#define SEQ 199
#define LSEQ 200
#define EMB 512
#define HID 512
#define G4H 2048
#define NLAY 5
#define NFC1 512
#define NFC2 256
#define SIGMA_MIX 0.5f

#define SMEM_SWIZZLE_128B(b) ((b) ^ (((b) >> 3) & 0x70))

__device__ __forceinline__ uint32_t smem_to_u32(const void* p) {
    uint32_t a;
    asm("{ .reg .u64 t; cvta.to.shared.u64 t, %1; cvt.u32.u64 %0, t; }" : "=r"(a) : "l"(p));
    return a;
}
__device__ __forceinline__ void cp_async16(uint32_t saddr, const void* gaddr) {
    asm volatile("cp.async.cg.shared.global [%0], [%1], 16;" :: "r"(saddr), "l"(gaddr));
}
#define CP_COMMIT() asm volatile("cp.async.commit_group;" ::: "memory")
#define CP_WAIT(N)  asm volatile("cp.async.wait_group %0;" :: "n"(N) : "memory")

__device__ __forceinline__ void ldmatrix_x4(uint32_t* r, uint32_t addr) {
    asm volatile("ldmatrix.sync.aligned.m8n8.x4.shared.b16 {%0,%1,%2,%3}, [%4];"
                 : "=r"(r[0]), "=r"(r[1]), "=r"(r[2]), "=r"(r[3]) : "r"(addr));
}
__device__ __forceinline__ void mma_f16(float* d, const uint32_t* a, uint32_t b0, uint32_t b1) {
    asm volatile("mma.sync.aligned.m16n8k16.row.col.f32.f16.f16.f32 "
                 "{%0,%1,%2,%3}, {%4,%5,%6,%7}, {%8,%9}, {%0,%1,%2,%3};"
                 : "+f"(d[0]), "+f"(d[1]), "+f"(d[2]), "+f"(d[3])
                 : "r"(a[0]), "r"(a[1]), "r"(a[2]), "r"(a[3]), "r"(b0), "r"(b1));
}

// recurrence B smem addressing: row n = 1024B; XOR in-segment 16B chunk bits with n&7
__device__ __forceinline__ uint32_t baddr(int n, int kb) {
    return (uint32_t)(n * 1024 + (kb ^ ((n & 7) << 4)));
}

// ---------------------------------------------------------------------------
// Static device scratch
// ---------------------------------------------------------------------------
__device__ float d_qa  [(size_t)LSEQ*BATCH*HID];
__device__ float d_qemb[(size_t)LSEQ*BATCH*HID];
__device__ float d_x0  [(size_t)LSEQ*BATCH*HID];   // fp32 lstm out (last layer only)
__device__ float d_gx  [(size_t)LSEQ*BATCH*G4H];
__device__ float d_t0  [(size_t)LSEQ*BATCH*HID];
__device__ float d_g0  [(size_t)LSEQ*BATCH*HID];   // final GCN out
__device__ float d_m2  [(size_t)BATCH*SEQ*NFC2];
__device__ float d_bsum[(size_t)NLAY*G4H];
__device__ unsigned d_gsync[2];
__device__ __half d_ah  [(size_t)LSEQ*BATCH*1024];
__device__ __half d_al  [(size_t)LSEQ*BATCH*1024];
__device__ __half d_bh  [(size_t)G4H*HID];
__device__ __half d_bl  [(size_t)G4H*HID];
__device__ __half d_hsh [(size_t)LSEQ*BATCH*HID];   // full-seq h hi (multi-use)
__device__ __half d_hsl [(size_t)LSEQ*BATCH*HID];   // full-seq h lo

__device__ __forceinline__ float sigf(float x) { return 1.0f / (1.0f + expf(-x)); }

// ---------------------------------------------------------------------------
// fp16 fused-3-group NT GEMM: out = act(A@B^T + bias), fp32 accum.
// Groups per k-step: Ahi*Bhi + Alo*Bhi + Ahi*Blo (drop lo*lo).
// 3-stage cp.async pipeline, tile 128x128x64, 8 warps, warp tile 32x64.
// Output: fp32 C (if non-null) and/or fp16 hi/lo pair (if Chi non-null).
// ---------------------------------------------------------------------------
#define MMA_SMEM 196608

__global__ __launch_bounds__(256)
void mma_gemm(const __half* __restrict__ Ahi, const __half* __restrict__ Alo,
              const __half* __restrict__ Bhi, const __half* __restrict__ Blo,
              float* __restrict__ C, __half* __restrict__ Chi, __half* __restrict__ Clo,
              int N, int K, const float* __restrict__ bias, int relu)
{
    extern __shared__ char smem[];
    const uint32_t smem_u = smem_to_u32(smem);
    const int tid = threadIdx.x;
    const int wid = tid >> 5, lane = tid & 31;
    const int warp_m = wid & 3, warp_n = wid >> 2;
    const long bm = (long)blockIdx.y * 128;
    const long bn = (long)blockIdx.x * 128;
    const int TI = K >> 6;

    float acc[2][8][4];
#pragma unroll
    for (int i = 0; i < 2; i++)
#pragma unroll
        for (int j = 0; j < 8; j++)
#pragma unroll
            for (int k = 0; k < 4; k++) acc[i][j][k] = 0.0f;

    // stage layout: Ahi @0, Alo @16384, Bhi @32768, Blo @49152 (stage stride 65536)
    auto issue_load = [&](int stage, int kt) {
        const long k0 = (long)kt << 6;
        const uint32_t s0 = smem_u + stage * 65536;
#pragma unroll
        for (int c0 = 0; c0 < 4; c0++) {
            const int cid = tid + c0 * 256;
            const int row = cid >> 3;
            const int o16 = cid & 7;
            const uint32_t sw = SMEM_SWIZZLE_128B((uint32_t)(row * 128 + o16 * 16));
            const long aoff = (bm + row) * (long)K + k0 + o16 * 8;
            const long boff = (bn + row) * (long)K + k0 + o16 * 8;
            cp_async16(s0 + sw,         Ahi + aoff);
            cp_async16(s0 + 16384 + sw, Alo + aoff);
            cp_async16(s0 + 32768 + sw, Bhi + boff);
            cp_async16(s0 + 49152 + sw, Blo + boff);
        }
    };

    issue_load(0, 0); CP_COMMIT();
    issue_load(1, 1); CP_COMMIT();

    for (int j = 0; j < TI; j++) {
        if (j + 2 < TI)      { issue_load((j + 2) % 3, j + 2); CP_COMMIT(); CP_WAIT(2); }
        else if (j + 1 < TI) { CP_WAIT(1); }
        else                 { CP_WAIT(0); }
        __syncthreads();

        const uint32_t s0 = smem_u + (j % 3) * 65536;
#pragma unroll
        for (int ks = 0; ks < 4; ks++) {
            uint32_t afh[2][4], afl[2][4];
#pragma unroll
            for (int mt = 0; mt < 2; mt++) {
                const int row = warp_m * 32 + mt * 16 + (lane & 15);
                const int col = ks * 32 + (lane >> 4) * 16;
                const uint32_t sw = SMEM_SWIZZLE_128B((uint32_t)(row * 128 + col));
                ldmatrix_x4(afh[mt], s0 + sw);
                ldmatrix_x4(afl[mt], s0 + 16384 + sw);
            }
            uint32_t bfh[4][4], bfl[4][4];
#pragma unroll
            for (int nt2 = 0; nt2 < 4; nt2++) {
                const int nrow = warp_n * 64 + nt2 * 16 + ((lane >> 4) << 3) + (lane & 7);
                const int col = ks * 32 + ((lane >> 3) & 1) * 16;
                const uint32_t sw = SMEM_SWIZZLE_128B((uint32_t)(nrow * 128 + col));
                ldmatrix_x4(bfh[nt2], s0 + 32768 + sw);
                ldmatrix_x4(bfl[nt2], s0 + 49152 + sw);
            }
#pragma unroll
            for (int mt = 0; mt < 2; mt++)
#pragma unroll
                for (int nt = 0; nt < 8; nt++) {
                    const uint32_t b0 = bfh[nt >> 1][(nt & 1) * 2 + 0];
                    const uint32_t b1 = bfh[nt >> 1][(nt & 1) * 2 + 1];
                    mma_f16(acc[mt][nt], afh[mt], b0, b1);
                    mma_f16(acc[mt][nt], afl[mt], b0, b1);
                    mma_f16(acc[mt][nt], afh[mt],
                            bfl[nt >> 1][(nt & 1) * 2 + 0],
                            bfl[nt >> 1][(nt & 1) * 2 + 1]);
                }
        }
        __syncthreads();
    }

#pragma unroll
    for (int mt = 0; mt < 2; mt++) {
        const long m0 = bm + warp_m * 32 + mt * 16 + (lane >> 2);
#pragma unroll
        for (int nt = 0; nt < 8; nt++) {
            const long nn = bn + warp_n * 64 + nt * 8 + (lane & 3) * 2;
            float bx = 0.0f, by = 0.0f;
            if (bias) { const float2 bv = *reinterpret_cast<const float2*>(&bias[nn]); bx = bv.x; by = bv.y; }
            float v0 = acc[mt][nt][0] + bx, v1 = acc[mt][nt][1] + by;
            float v2 = acc[mt][nt][2] + bx, v3 = acc[mt][nt][3] + by;
            if (relu) {
                v0 = fmaxf(v0, 0.0f); v1 = fmaxf(v1, 0.0f);
                v2 = fmaxf(v2, 0.0f); v3 = fmaxf(v3, 0.0f);
            }
            if (C) {
                *reinterpret_cast<float2*>(&C[m0 * (long)N + nn])       = make_float2(v0, v1);
                *reinterpret_cast<float2*>(&C[(m0 + 8) * (long)N + nn]) = make_float2(v2, v3);
            }
            if (Chi) {
                __half h0 = __float2half(v0), h1 = __float2half(v1);
                __half h2 = __float2half(v2), h3 = __float2half(v3);
                __half l0 = __float2half(v0 - __half2float(h0));
                __half l1 = __float2half(v1 - __half2float(h1));
                __half l2 = __float2half(v2 - __half2float(h2));
                __half l3 = __float2half(v3 - __half2float(h3));
                *reinterpret_cast<__half2*>(&Chi[m0 * (long)N + nn])       = __halves2half2(h0, h1);
                *reinterpret_cast<__half2*>(&Chi[(m0 + 8) * (long)N + nn]) = __halves2half2(h2, h3);
                *reinterpret_cast<__half2*>(&Clo[m0 * (long)N + nn])       = __halves2half2(l0, l1);
                *reinterpret_cast<__half2*>(&Clo[(m0 + 8) * (long)N + nn]) = __halves2half2(l2, l3);
            }
        }
    }
}

// ---------------------------------------------------------------------------
// Persistent tensor-core LSTM layer (3-pass fp16 split). 128 blocks x 128 thr.
// Writes h hi/lo into full-seq hseq buffers; fp32 out only if out != null.
// phase0 offsets the grid-barrier epoch so one memset serves all 5 layers.
// ---------------------------------------------------------------------------
#define LSTM2_SMEM 163840

__global__ __launch_bounds__(128)
void lstm_layer_mma(const float* __restrict__ gx, const float* __restrict__ Whh,
                    float* __restrict__ out,
                    __half* __restrict__ hsh, __half* __restrict__ hsl,
                    unsigned phase0)
{
    extern __shared__ char smem[];
    const uint32_t smem_u = smem_to_u32(smem);
    const uint32_t Ast_u = smem_u + 131072;

    const int tid = threadIdx.x;
    const int wid = tid >> 5, lane = tid & 31;
    const int bm = (blockIdx.x & 3) * 64;
    const int c0 = (blockIdx.x >> 2) * 16;

    for (int i = tid; i < 64 * 512; i += 128) {
        const int n = i >> 9, k = i & 511;
        const int g = n >> 4, hl = n & 15;
        const float w = Whh[(size_t)(g * 512 + c0 + hl) * 512 + k];
        const __half h = __float2half(w);
        const __half l = __float2half(w - __half2float(h));
        const uint32_t off = baddr(n, k * 2);
        *reinterpret_cast<__half*>(smem + off) = h;
        *reinterpret_cast<__half*>(smem + 65536 + off) = l;
    }
    __syncthreads();

    float creg[8];
#pragma unroll
    for (int i = 0; i < 8; i++) creg[i] = 0.0f;
    unsigned phase = phase0;

    for (int t = 0; t < LSEQ; t++) {
        float acc[8][4];
#pragma unroll
        for (int i = 0; i < 8; i++)
#pragma unroll
            for (int j = 0; j < 4; j++) acc[i][j] = 0.0f;

        if (t > 0) {
            const __half* hhi = hsh + (size_t)(t - 1) * BATCH * HID;
            const __half* hlo = hsl + (size_t)(t - 1) * BATCH * HID;

            auto issueA = [&](int stage, int kc) {
                const uint32_t sa = Ast_u + stage * 16384;
#pragma unroll
                for (int c = 0; c < 4; c++) {
                    const int cid = tid + c * 128;
                    const int row = cid >> 3, o16 = cid & 7;
                    const uint32_t sw = SMEM_SWIZZLE_128B((uint32_t)(row * 128 + o16 * 16));
                    cp_async16(sa + sw,        hhi + (bm + row) * 512 + kc * 64 + o16 * 8);
                    cp_async16(sa + 8192 + sw, hlo + (bm + row) * 512 + kc * 64 + o16 * 8);
                }
            };
            issueA(0, 0);
            CP_COMMIT();
            for (int kc = 0; kc < 8; kc++) {
                if (kc < 7) { issueA((kc + 1) & 1, kc + 1); CP_COMMIT(); CP_WAIT(1); }
                else        { CP_WAIT(0); }
                __syncthreads();
                const uint32_t sa = Ast_u + (kc & 1) * 16384;
#pragma unroll
                for (int ks = 0; ks < 4; ks++) {
                    uint32_t ahf[4], alf[4];
                    {
                        const int row = wid * 16 + (lane & 15);
                        const int col = ks * 32 + (lane >> 4) * 16;
                        const uint32_t ad = sa + SMEM_SWIZZLE_128B((uint32_t)(row * 128 + col));
                        ldmatrix_x4(ahf, ad);
                        ldmatrix_x4(alf, ad + 8192);
                    }
                    uint32_t bhf[4][4], blf[4][4];
#pragma unroll
                    for (int g2 = 0; g2 < 4; g2++) {
                        const int n_r = g2 * 16 + ((lane >> 4) << 3) + (lane & 7);
                        const int kb = (ks * 16 + ((lane >> 3) & 1) * 8) * 2 + kc * 128;
                        const uint32_t off = baddr(n_r, kb);
                        ldmatrix_x4(bhf[g2], smem_u + off);
                        ldmatrix_x4(blf[g2], smem_u + 65536 + off);
                    }
#pragma unroll
                    for (int nt = 0; nt < 8; nt++) {
                        const uint32_t b0 = bhf[nt >> 1][(nt & 1) * 2 + 0];
                        const uint32_t b1 = bhf[nt >> 1][(nt & 1) * 2 + 1];
                        mma_f16(acc[nt], ahf, b0, b1);
                        mma_f16(acc[nt], alf, b0, b1);
                        mma_f16(acc[nt], ahf,
                                blf[nt >> 1][(nt & 1) * 2 + 0],
                                blf[nt >> 1][(nt & 1) * 2 + 1]);
                    }
                }
                __syncthreads();
            }
        }

        // ---- fused pointwise (gate-major acc: nt = g*2 + hb) ----
        {
            __half* whi = hsh + (size_t)t * BATCH * HID;
            __half* wlo = hsl + (size_t)t * BATCH * HID;
            float* outp = out ? out + (size_t)t * BATCH * HID : nullptr;
            const float* gxp = gx + (size_t)t * BATCH * G4H;
#pragma unroll
            for (int rh = 0; rh < 2; rh++) {
                const int b = bm + wid * 16 + (lane >> 2) + rh * 8;
                const size_t gb = (size_t)b * G4H + c0;
#pragma unroll
                for (int hb = 0; hb < 2; hb++) {
#pragma unroll
                    for (int cc = 0; cc < 2; cc++) {
                        const int hl = hb * 8 + (lane & 3) * 2 + cc;
                        const int ci = rh * 4 + hb * 2 + cc;
                        const int jj = rh * 2 + cc;
                        const float gi = gxp[gb + hl]              + acc[0 + hb][jj];
                        const float gf = gxp[gb + 512 + hl]        + acc[2 + hb][jj];
                        const float gg = gxp[gb + 1024 + hl]       + acc[4 + hb][jj];
                        const float go = gxp[gb + 1536 + hl]       + acc[6 + hb][jj];
                        const float cv = sigf(gf) * creg[ci] + sigf(gi) * tanhf(gg);
                        const float hv = sigf(go) * tanhf(cv);
                        creg[ci] = cv;
                        if (outp) outp[(size_t)b * HID + c0 + hl] = hv;
                        const __half hh = __float2half(hv);
                        whi[b * HID + c0 + hl] = hh;
                        wlo[b * HID + c0 + hl] = __float2half(hv - __half2float(hh));
                    }
                }
            }
        }

        // ---- grid barrier (flag-based, cross-layer epochs) ----
        __syncthreads();
        if (tid == 0) {
            __threadfence();
            const unsigned old = atomicAdd(&d_gsync[0], 1u);
            if (old == phase * 128u + 127u) {
                atomicExch(&d_gsync[1], phase + 1u);
            } else {
                while (*((volatile unsigned*)&d_gsync[1]) <= phase) {}
            }
            __threadfence();
        }
        __syncthreads();
        phase++;
    }
}

// ---------------------------------------------------------------------------
// fp32 -> fp16 hi/lo split (A and [N,K] weights)
// ---------------------------------------------------------------------------
__global__ void split_k(const float* __restrict__ A,
                        __half* __restrict__ hi, __half* __restrict__ lo, long n)
{
    const long i = ((long)blockIdx.x * blockDim.x + threadIdx.x) * 4;
    if (i >= n) return;
    const float4 v = *reinterpret_cast<const float4*>(A + i);
    float a[4] = {v.x, v.y, v.z, v.w};
    __half h[4], l[4];
#pragma unroll
    for (int k = 0; k < 4; k++) {
        h[k] = __float2half(a[k]);
        l[k] = __float2half(a[k] - __half2float(h[k]));
    }
    *reinterpret_cast<uint2*>(hi + i) = *reinterpret_cast<uint2*>(h);
    *reinterpret_cast<uint2*>(lo + i) = *reinterpret_cast<uint2*>(l);
}

// transposing fp32 [K,N] -> fp16 hi/lo [N,K]
__global__ void splitT_k(const float* __restrict__ in,
                         __half* __restrict__ hi, __half* __restrict__ lo,
                         int K, int N)
{
    __shared__ float tile[32][33];
    int x = blockIdx.x * 32 + threadIdx.x;
    int y = blockIdx.y * 32 + threadIdx.y;
    if (x < N && y < K) tile[threadIdx.y][threadIdx.x] = in[(size_t)y * N + x];
    __syncthreads();
    const int n = blockIdx.x * 32 + threadIdx.y;
    const int k = blockIdx.y * 32 + threadIdx.x;
    if (n < N && k < K) {
        const float w = tile[threadIdx.x][threadIdx.y];
        const __half h = __float2half(w);
        hi[(size_t)n * K + k] = h;
        lo[(size_t)n * K + k] = __float2half(w - __half2float(h));
    }
}

// ---------------------------------------------------------------------------
// Adjacency contraction. If blend != null: instead of storing fp32 C, emits
// fp16 hi/lo of  0.5*act(result) + 0.5*blend  (the GCN residual mix).
// ---------------------------------------------------------------------------
__launch_bounds__(256)
__global__ void adj_gemm(const float* __restrict__ adj, const float* __restrict__ T,
                         float* __restrict__ C, int relu,
                         const float* __restrict__ blend,
                         __half* __restrict__ ohi, __half* __restrict__ olo)
{
    constexpr int RB = 25;
    constexpr int N = BATCH * HID;
    __shared__ float as[RB][LSEQ];
    const int r0 = blockIdx.y * RB;
    const int n  = blockIdx.x * 256 + threadIdx.x;

    for (int i = threadIdx.x; i < RB * LSEQ; i += 256)
        as[i / LSEQ][i % LSEQ] = adj[(size_t)(r0 + i / LSEQ) * LSEQ + (i % LSEQ)];
    __syncthreads();

    float acc[RB];
#pragma unroll
    for (int r = 0; r < RB; r++) acc[r] = 0.0f;
    for (int k = 0; k < LSEQ; k++) {
        const float t = T[(size_t)k * N + n];
#pragma unroll
        for (int r = 0; r < RB; r++) acc[r] = fmaf(as[r][k], t, acc[r]);
    }
#pragma unroll
    for (int r = 0; r < RB; r++) {
        float v = acc[r];
        if (relu) v = fmaxf(v, 0.0f);
        const size_t idx = (size_t)(r0 + r) * N + n;
        if (blend) {
            const float m = (1.0f - SIGMA_MIX) * v + SIGMA_MIX * blend[idx];
            const __half h = __float2half(m);
            ohi[idx] = h;
            olo[idx] = __float2half(m - __half2float(h));
        } else {
            C[idx] = v;
        }
    }
}

// ---------------------------------------------------------------------------
// Embedding / misc
// ---------------------------------------------------------------------------
__global__ void embed_k(const int* __restrict__ q, const int* __restrict__ c,
                        const int* __restrict__ r, const int* __restrict__ qsh,
                        const int* __restrict__ csh, const int* __restrict__ rsh,
                        const float* __restrict__ Wq, const float* __restrict__ Wc,
                        const float* __restrict__ Wr,
                        float* __restrict__ qa, float* __restrict__ qemb)
{
    const long idx = (long)blockIdx.x * blockDim.x + threadIdx.x;
    if (idx >= (long)LSEQ * BATCH * HID) return;
    const int e = (int)(idx % HID);
    const int b = (int)((idx / HID) % BATCH);
    const int t = (int)(idx / ((long)HID * BATCH));
    const int pid = (t == 0) ? q[b * SEQ]  : qsh[b * SEQ + t - 1];
    const int cid = (t == 0) ? c[b * SEQ]  : csh[b * SEQ + t - 1];
    const int tgt = (t == 0) ? r[b * SEQ]  : rsh[b * SEQ + t - 1];
    const float qe = Wq[(size_t)pid * EMB + e] + Wc[(size_t)cid * EMB + e];
    qemb[idx] = qe;
    qa[idx]   = qe + Wr[(size_t)tgt * EMB + e];
}

__global__ void bsum_k(const float* __restrict__ bih, const float* __restrict__ bhh,
                       float* __restrict__ bsum)
{
    const int i = blockIdx.x * blockDim.x + threadIdx.x;
    if (i < NLAY * G4H) bsum[i] = bih[i] + bhh[i];
}

// concat emitting fp16 hi/lo directly (feeds fc1 GEMM only)
__global__ void concat_half_k(const float* __restrict__ hg, const float* __restrict__ qe,
                              __half* __restrict__ hi, __half* __restrict__ lo)
{
    const long idx = (long)blockIdx.x * blockDim.x + threadIdx.x;
    if (idx >= (long)BATCH * SEQ * (2 * EMB)) return;
    const int f = (int)(idx % (2 * EMB));
    const int s = (int)((idx / (2 * EMB)) % SEQ);
    const int b = (int)(idx / ((long)(2 * EMB) * SEQ));
    const size_t src = ((size_t)(s + 1) * BATCH + b) * HID;
    const float v = (f < EMB) ? hg[src + f] : qe[src + (f - EMB)];
    const __half h = __float2half(v);
    hi[idx] = h;
    lo[idx] = __float2half(v - __half2float(h));
}

__global__ void mlp3_k(const float* __restrict__ X, const float* __restrict__ W3,
                       const float* __restrict__ b3, float* __restrict__ y, int M)
{
    const int warp = (blockIdx.x * blockDim.x + threadIdx.x) >> 5;
    const int lane = threadIdx.x & 31;
    if (warp >= M) return;
    const float* xr = X + (size_t)warp * NFC2;
    float s = 0.0f;
#pragma unroll
    for (int k = lane; k < NFC2; k += 32) s = fmaf(xr[k], W3[k], s);
#pragma unroll
    for (int o = 16; o > 0; o >>= 1) s += __shfl_down_sync(0xffffffffu, s, o);
    if (lane == 0) y[warp] = 1.0f / (1.0f + expf(-(s + b3[0])));
}

// ---------------------------------------------------------------------------
// Orchestration
// ---------------------------------------------------------------------------
extern "C" void kernel_launch(void* const* d_in, const int* in_sizes, int n_in,
                              void* d_out, int out_size)
{
    const int   *q   = (const int*)d_in[0],  *c   = (const int*)d_in[1];
    const int   *r   = (const int*)d_in[2],  *qsh = (const int*)d_in[3];
    const int   *csh = (const int*)d_in[4],  *rsh = (const int*)d_in[5];
    const float *adj = (const float*)d_in[6];
    const float *Wq  = (const float*)d_in[7], *Wc  = (const float*)d_in[8];
    const float *Wr  = (const float*)d_in[9];
    const float *Wih = (const float*)d_in[10], *Whh = (const float*)d_in[11];
    const float *bih = (const float*)d_in[12], *bhh = (const float*)d_in[13];
    const float *Wg  = (const float*)d_in[14];
    const float *W1  = (const float*)d_in[15], *b1 = (const float*)d_in[16];
    const float *W2  = (const float*)d_in[17], *b2 = (const float*)d_in[18];
    const float *W3  = (const float*)d_in[19], *b3 = (const float*)d_in[20];
    float* y = (float*)d_out;

    float *qa, *qemb, *x0, *gx, *t0, *g0, *m2, *bsum;
    unsigned* gsync;
    __half *ah, *al, *bh, *bl, *hsh, *hsl;
    cudaGetSymbolAddress((void**)&qa,   d_qa);
    cudaGetSymbolAddress((void**)&qemb, d_qemb);
    cudaGetSymbolAddress((void**)&x0,   d_x0);
    cudaGetSymbolAddress((void**)&gx,   d_gx);
    cudaGetSymbolAddress((void**)&t0,   d_t0);
    cudaGetSymbolAddress((void**)&g0,   d_g0);
    cudaGetSymbolAddress((void**)&m2,   d_m2);
    cudaGetSymbolAddress((void**)&bsum, d_bsum);
    cudaGetSymbolAddress((void**)&gsync, d_gsync);
    cudaGetSymbolAddress((void**)&ah,   d_ah);
    cudaGetSymbolAddress((void**)&al,   d_al);
    cudaGetSymbolAddress((void**)&bh,   d_bh);
    cudaGetSymbolAddress((void**)&bl,   d_bl);
    cudaGetSymbolAddress((void**)&hsh,  d_hsh);
    cudaGetSymbolAddress((void**)&hsl,  d_hsl);

    cudaFuncSetAttribute(mma_gemm, cudaFuncAttributeMaxDynamicSharedMemorySize, MMA_SMEM);
    cudaFuncSetAttribute(lstm_layer_mma, cudaFuncAttributeMaxDynamicSharedMemorySize, LSTM2_SMEM);

    const long NE = (long)LSEQ * BATCH * HID;

    // ---- prep (launch #6 = first big mma_gemm, for ncu -s 5 -c 1) ----
    bsum_k<<<(NLAY * G4H + 255) / 256, 256>>>(bih, bhh, bsum);                // 1
    {
        const long n = NE;
        embed_k<<<(unsigned)((n + 255) / 256), 256>>>(q, c, r, qsh, csh, rsh,
                                                      Wq, Wc, Wr, qa, qemb);  // 2
    }
    cudaMemsetAsync(gsync, 0, 8, 0);                                          // 3
    split_k<<<(unsigned)(NE / 4 / 256), 256>>>(qa, hsh, hsl, NE);             // 4

    // ---- 5-layer LSTM: hseq carries hi/lo activations across layers ----
    for (int l = 0; l < NLAY; l++) {
        split_k<<<(unsigned)((long)G4H * HID / 4 / 256), 256>>>(
            Wih + (size_t)l * G4H * HID, bh, bl, (long)G4H * HID);            // 5
        mma_gemm<<<dim3(G4H / 128, (LSEQ * BATCH) / 128), 256, MMA_SMEM>>>(
            hsh, hsl, bh, bl, gx, nullptr, nullptr, G4H, HID,
            bsum + (size_t)l * G4H, 0);                                       // 6 <- ncu
        lstm_layer_mma<<<128, 128, LSTM2_SMEM>>>(
            gx, Whh + (size_t)l * G4H * HID,
            (l == NLAY - 1) ? x0 : nullptr, hsh, hsl, (unsigned)(l * LSEQ));
    }
    const float* lstm_out = x0;

    // ---- 5 GCN layers (blend-split fused into adj_gemm epilogue) ----
    splitT_k<<<dim3(16, 16), dim3(32, 32)>>>(Wg, bh, bl, HID, HID);
    mma_gemm<<<dim3(HID / 128, (LSEQ * BATCH) / 128), 256, MMA_SMEM>>>(
        hsh, hsl, bh, bl, t0, nullptr, nullptr, HID, HID, nullptr, 0);
    adj_gemm<<<dim3((BATCH * HID) / 256, LSEQ / 25), 256>>>(
        adj, t0, nullptr, 1, lstm_out, ah, al);
    for (int i = 1; i < 5; i++) {
        splitT_k<<<dim3(16, 16), dim3(32, 32)>>>(Wg + (size_t)i * HID * HID, bh, bl,
                                                 HID, HID);
        mma_gemm<<<dim3(HID / 128, (LSEQ * BATCH) / 128), 256, MMA_SMEM>>>(
            ah, al, bh, bl, t0, nullptr, nullptr, HID, HID, nullptr, 0);
        if (i < 4) {
            adj_gemm<<<dim3((BATCH * HID) / 256, LSEQ / 25), 256>>>(
                adj, t0, nullptr, 1, lstm_out, ah, al);
        } else {
            adj_gemm<<<dim3((BATCH * HID) / 256, LSEQ / 25), 256>>>(
                adj, t0, g0, 0, nullptr, nullptr, nullptr);
        }
    }

    // ---- concat + MLP head (splits fused into producers) ----
    {
        const long n = (long)BATCH * SEQ * (2 * EMB);
        concat_half_k<<<(unsigned)((n + 255) / 256), 256>>>(g0, qemb, ah, al);
    }
    const int M = BATCH * SEQ;   // 50944 = 398*128
    splitT_k<<<dim3(16, 32), dim3(32, 32)>>>(W1, bh, bl, 2 * EMB, NFC1);
    mma_gemm<<<dim3(NFC1 / 128, M / 128), 256, MMA_SMEM>>>(
        ah, al, bh, bl, nullptr, hsh, hsl, NFC1, 2 * EMB, b1, 1);
    splitT_k<<<dim3(8, 16), dim3(32, 32)>>>(W2, bh, bl, NFC1, NFC2);
    mma_gemm<<<dim3(NFC2 / 128, M / 128), 256, MMA_SMEM>>>(
        hsh, hsl, bh, bl, m2, nullptr, nullptr, NFC2, NFC1, b2, 1);
    mlp3_k<<<(M * 32 + 255) / 256, 256>>>(m2, W3, b3, y, M);
}

// round 12
// speedup vs baseline: 1.0518x; 1.0518x over previous
#include <cuda_runtime.h>
#include <cuda_fp16.h>
#include <math.h>
#include <stdint.h>

#define BATCH 256
#define SEQ 199
#define LSEQ 200
#define EMB 512
#define HID 512
#define G4H 2048
#define NLAY 5
#define NFC1 512
#define NFC2 256
#define SIGMA_MIX 0.5f

#define SMEM_SWIZZLE_128B(b) ((b) ^ (((b) >> 3) & 0x70))

__device__ __forceinline__ uint32_t smem_to_u32(const void* p) {
    uint32_t a;
    asm("{ .reg .u64 t; cvta.to.shared.u64 t, %1; cvt.u32.u64 %0, t; }" : "=r"(a) : "l"(p));
    return a;
}
__device__ __forceinline__ void cp_async16(uint32_t saddr, const void* gaddr) {
    asm volatile("cp.async.cg.shared.global [%0], [%1], 16;" :: "r"(saddr), "l"(gaddr));
}
#define CP_COMMIT() asm volatile("cp.async.commit_group;" ::: "memory")
#define CP_WAIT(N)  asm volatile("cp.async.wait_group %0;" :: "n"(N) : "memory")

__device__ __forceinline__ void ldmatrix_x4(uint32_t* r, uint32_t addr) {
    asm volatile("ldmatrix.sync.aligned.m8n8.x4.shared.b16 {%0,%1,%2,%3}, [%4];"
                 : "=r"(r[0]), "=r"(r[1]), "=r"(r[2]), "=r"(r[3]) : "r"(addr));
}
__device__ __forceinline__ void mma_f16(float* d, const uint32_t* a, uint32_t b0, uint32_t b1) {
    asm volatile("mma.sync.aligned.m16n8k16.row.col.f32.f16.f16.f32 "
                 "{%0,%1,%2,%3}, {%4,%5,%6,%7}, {%8,%9}, {%0,%1,%2,%3};"
                 : "+f"(d[0]), "+f"(d[1]), "+f"(d[2]), "+f"(d[3])
                 : "r"(a[0]), "r"(a[1]), "r"(a[2]), "r"(a[3]), "r"(b0), "r"(b1));
}

// recurrence B smem addressing: row n = 1024B; XOR in-segment 16B chunk bits with n&7
__device__ __forceinline__ uint32_t baddr(int n, int kb) {
    return (uint32_t)(n * 1024 + (kb ^ ((n & 7) << 4)));
}

// ---------------------------------------------------------------------------
// Static device scratch
// ---------------------------------------------------------------------------
__device__ float d_qemb[(size_t)LSEQ*BATCH*HID];
__device__ float d_x0  [(size_t)LSEQ*BATCH*HID];   // fp32 lstm out (last layer only)
__device__ float d_gx  [(size_t)LSEQ*BATCH*G4H];
__device__ float d_t0  [(size_t)LSEQ*BATCH*HID];
__device__ float d_g0  [(size_t)LSEQ*BATCH*HID];   // final GCN out
__device__ float d_m2  [(size_t)BATCH*SEQ*NFC2];
__device__ float d_bsum[(size_t)NLAY*G4H];
__device__ unsigned d_gsync[2];
__device__ __half d_ah  [(size_t)LSEQ*BATCH*1024];
__device__ __half d_al  [(size_t)LSEQ*BATCH*1024];
__device__ __half d_bh  [(size_t)G4H*HID];
__device__ __half d_bl  [(size_t)G4H*HID];
__device__ __half d_hsh [(size_t)LSEQ*BATCH*HID];   // full-seq h hi (multi-use)
__device__ __half d_hsl [(size_t)LSEQ*BATCH*HID];   // full-seq h lo

__device__ __forceinline__ float sigf(float x) { return 1.0f / (1.0f + expf(-x)); }

// ---------------------------------------------------------------------------
// fp16 fused-3-group NT GEMM (unchanged from R9/R10 core).
// ---------------------------------------------------------------------------
#define MMA_SMEM 196608

__global__ __launch_bounds__(256)
void mma_gemm(const __half* __restrict__ Ahi, const __half* __restrict__ Alo,
              const __half* __restrict__ Bhi, const __half* __restrict__ Blo,
              float* __restrict__ C, __half* __restrict__ Chi, __half* __restrict__ Clo,
              int N, int K, const float* __restrict__ bias, int relu)
{
    extern __shared__ char smem[];
    const uint32_t smem_u = smem_to_u32(smem);
    const int tid = threadIdx.x;
    const int wid = tid >> 5, lane = tid & 31;
    const int warp_m = wid & 3, warp_n = wid >> 2;
    const long bm = (long)blockIdx.y * 128;
    const long bn = (long)blockIdx.x * 128;
    const int TI = K >> 6;

    float acc[2][8][4];
#pragma unroll
    for (int i = 0; i < 2; i++)
#pragma unroll
        for (int j = 0; j < 8; j++)
#pragma unroll
            for (int k = 0; k < 4; k++) acc[i][j][k] = 0.0f;

    auto issue_load = [&](int stage, int kt) {
        const long k0 = (long)kt << 6;
        const uint32_t s0 = smem_u + stage * 65536;
#pragma unroll
        for (int c0 = 0; c0 < 4; c0++) {
            const int cid = tid + c0 * 256;
            const int row = cid >> 3;
            const int o16 = cid & 7;
            const uint32_t sw = SMEM_SWIZZLE_128B((uint32_t)(row * 128 + o16 * 16));
            const long aoff = (bm + row) * (long)K + k0 + o16 * 8;
            const long boff = (bn + row) * (long)K + k0 + o16 * 8;
            cp_async16(s0 + sw,         Ahi + aoff);
            cp_async16(s0 + 16384 + sw, Alo + aoff);
            cp_async16(s0 + 32768 + sw, Bhi + boff);
            cp_async16(s0 + 49152 + sw, Blo + boff);
        }
    };

    issue_load(0, 0); CP_COMMIT();
    issue_load(1, 1); CP_COMMIT();

    for (int j = 0; j < TI; j++) {
        if (j + 2 < TI)      { issue_load((j + 2) % 3, j + 2); CP_COMMIT(); CP_WAIT(2); }
        else if (j + 1 < TI) { CP_WAIT(1); }
        else                 { CP_WAIT(0); }
        __syncthreads();

        const uint32_t s0 = smem_u + (j % 3) * 65536;
#pragma unroll
        for (int ks = 0; ks < 4; ks++) {
            uint32_t afh[2][4], afl[2][4];
#pragma unroll
            for (int mt = 0; mt < 2; mt++) {
                const int row = warp_m * 32 + mt * 16 + (lane & 15);
                const int col = ks * 32 + (lane >> 4) * 16;
                const uint32_t sw = SMEM_SWIZZLE_128B((uint32_t)(row * 128 + col));
                ldmatrix_x4(afh[mt], s0 + sw);
                ldmatrix_x4(afl[mt], s0 + 16384 + sw);
            }
            uint32_t bfh[4][4], bfl[4][4];
#pragma unroll
            for (int nt2 = 0; nt2 < 4; nt2++) {
                const int nrow = warp_n * 64 + nt2 * 16 + ((lane >> 4) << 3) + (lane & 7);
                const int col = ks * 32 + ((lane >> 3) & 1) * 16;
                const uint32_t sw = SMEM_SWIZZLE_128B((uint32_t)(nrow * 128 + col));
                ldmatrix_x4(bfh[nt2], s0 + 32768 + sw);
                ldmatrix_x4(bfl[nt2], s0 + 49152 + sw);
            }
#pragma unroll
            for (int mt = 0; mt < 2; mt++)
#pragma unroll
                for (int nt = 0; nt < 8; nt++) {
                    const uint32_t b0 = bfh[nt >> 1][(nt & 1) * 2 + 0];
                    const uint32_t b1 = bfh[nt >> 1][(nt & 1) * 2 + 1];
                    mma_f16(acc[mt][nt], afh[mt], b0, b1);
                    mma_f16(acc[mt][nt], afl[mt], b0, b1);
                    mma_f16(acc[mt][nt], afh[mt],
                            bfl[nt >> 1][(nt & 1) * 2 + 0],
                            bfl[nt >> 1][(nt & 1) * 2 + 1]);
                }
        }
        __syncthreads();
    }

#pragma unroll
    for (int mt = 0; mt < 2; mt++) {
        const long m0 = bm + warp_m * 32 + mt * 16 + (lane >> 2);
#pragma unroll
        for (int nt = 0; nt < 8; nt++) {
            const long nn = bn + warp_n * 64 + nt * 8 + (lane & 3) * 2;
            float bx = 0.0f, by = 0.0f;
            if (bias) { const float2 bv = *reinterpret_cast<const float2*>(&bias[nn]); bx = bv.x; by = bv.y; }
            float v0 = acc[mt][nt][0] + bx, v1 = acc[mt][nt][1] + by;
            float v2 = acc[mt][nt][2] + bx, v3 = acc[mt][nt][3] + by;
            if (relu) {
                v0 = fmaxf(v0, 0.0f); v1 = fmaxf(v1, 0.0f);
                v2 = fmaxf(v2, 0.0f); v3 = fmaxf(v3, 0.0f);
            }
            if (C) {
                *reinterpret_cast<float2*>(&C[m0 * (long)N + nn])       = make_float2(v0, v1);
                *reinterpret_cast<float2*>(&C[(m0 + 8) * (long)N + nn]) = make_float2(v2, v3);
            }
            if (Chi) {
                __half h0 = __float2half(v0), h1 = __float2half(v1);
                __half h2 = __float2half(v2), h3 = __float2half(v3);
                __half l0 = __float2half(v0 - __half2float(h0));
                __half l1 = __float2half(v1 - __half2float(h1));
                __half l2 = __float2half(v2 - __half2float(h2));
                __half l3 = __float2half(v3 - __half2float(h3));
                *reinterpret_cast<__half2*>(&Chi[m0 * (long)N + nn])       = __halves2half2(h0, h1);
                *reinterpret_cast<__half2*>(&Chi[(m0 + 8) * (long)N + nn]) = __halves2half2(h2, h3);
                *reinterpret_cast<__half2*>(&Clo[m0 * (long)N + nn])       = __halves2half2(l0, l1);
                *reinterpret_cast<__half2*>(&Clo[(m0 + 8) * (long)N + nn]) = __halves2half2(l2, l3);
            }
        }
    }
}

// ---------------------------------------------------------------------------
// Persistent tensor-core LSTM layer — now 256 threads / 8 warps (2 per SMSP).
// Warp grid 4(M)x2(N): warp tile 16x32. Gate mapping per 16-col chunk:
//   smem col n = chunk*16 + gpair*8 + hlq*2 + gsub
//   (hidden col hl = chunk*4 + hlq, gate g = gpair*2 + gsub)
// so each thread owns all 4 gates of its hidden column in its acc fragment.
// ---------------------------------------------------------------------------
#define LSTM2_SMEM 163840

__global__ __launch_bounds__(256)
void lstm_layer_mma(const float* __restrict__ gx, const float* __restrict__ Whh,
                    float* __restrict__ out,
                    __half* __restrict__ hsh, __half* __restrict__ hsl,
                    unsigned phase0)
{
    extern __shared__ char smem[];
    const uint32_t smem_u = smem_to_u32(smem);
    const uint32_t Ast_u = smem_u + 131072;

    const int tid = threadIdx.x;
    const int wid = tid >> 5, lane = tid & 31;
    const int warp_m = wid & 3;       // M slice: 16 rows
    const int warp_n = wid >> 2;      // N slice: 32 cols
    const int bm = (blockIdx.x & 3) * 64;
    const int c0 = (blockIdx.x >> 2) * 16;

    // ---- Whh slice -> smem fp16 hi/lo with gate-chunk mapping ----
    for (int i = tid; i < 64 * 512; i += 256) {
        const int n = i >> 9, k = i & 511;
        const int chunk = n >> 4, w16 = n & 15;
        const int gpair = w16 >> 3, rest = w16 & 7;
        const int hl = chunk * 4 + (rest >> 1);
        const int g  = gpair * 2 + (rest & 1);
        const float w = Whh[(size_t)(g * 512 + c0 + hl) * 512 + k];
        const __half h = __float2half(w);
        const __half l = __float2half(w - __half2float(h));
        const uint32_t off = baddr(n, k * 2);
        *reinterpret_cast<__half*>(smem + off) = h;
        *reinterpret_cast<__half*>(smem + 65536 + off) = l;
    }
    __syncthreads();

    float creg[4];
#pragma unroll
    for (int i = 0; i < 4; i++) creg[i] = 0.0f;
    unsigned phase = phase0;

    for (int t = 0; t < LSEQ; t++) {
        float acc[4][4];
#pragma unroll
        for (int i = 0; i < 4; i++)
#pragma unroll
            for (int j = 0; j < 4; j++) acc[i][j] = 0.0f;

        if (t > 0) {
            const __half* hhi = hsh + (size_t)(t - 1) * BATCH * HID;
            const __half* hlo = hsl + (size_t)(t - 1) * BATCH * HID;

            auto issueA = [&](int stage, int kc) {
                const uint32_t sa = Ast_u + stage * 16384;
#pragma unroll
                for (int c = 0; c < 2; c++) {
                    const int cid = tid + c * 256;      // 0..511 16B chunks
                    const int row = cid >> 3, o16 = cid & 7;
                    const uint32_t sw = SMEM_SWIZZLE_128B((uint32_t)(row * 128 + o16 * 16));
                    cp_async16(sa + sw,        hhi + (bm + row) * 512 + kc * 64 + o16 * 8);
                    cp_async16(sa + 8192 + sw, hlo + (bm + row) * 512 + kc * 64 + o16 * 8);
                }
            };
            issueA(0, 0);
            CP_COMMIT();
            for (int kc = 0; kc < 8; kc++) {
                if (kc < 7) { issueA((kc + 1) & 1, kc + 1); CP_COMMIT(); CP_WAIT(1); }
                else        { CP_WAIT(0); }
                __syncthreads();
                const uint32_t sa = Ast_u + (kc & 1) * 16384;
#pragma unroll
                for (int ks = 0; ks < 4; ks++) {
                    uint32_t ahf[4], alf[4];
                    {
                        const int row = warp_m * 16 + (lane & 15);
                        const int col = ks * 32 + (lane >> 4) * 16;
                        const uint32_t ad = sa + SMEM_SWIZZLE_128B((uint32_t)(row * 128 + col));
                        ldmatrix_x4(ahf, ad);
                        ldmatrix_x4(alf, ad + 8192);
                    }
                    uint32_t bhf[2][4], blf[2][4];
#pragma unroll
                    for (int g2 = 0; g2 < 2; g2++) {
                        const int n_r = warp_n * 32 + g2 * 16 + ((lane >> 4) << 3) + (lane & 7);
                        const int kb = (ks * 16 + ((lane >> 3) & 1) * 8) * 2 + kc * 128;
                        const uint32_t off = baddr(n_r, kb);
                        ldmatrix_x4(bhf[g2], smem_u + off);
                        ldmatrix_x4(blf[g2], smem_u + 65536 + off);
                    }
#pragma unroll
                    for (int nt = 0; nt < 4; nt++) {
                        const uint32_t b0 = bhf[nt >> 1][(nt & 1) * 2 + 0];
                        const uint32_t b1 = bhf[nt >> 1][(nt & 1) * 2 + 1];
                        mma_f16(acc[nt], ahf, b0, b1);
                        mma_f16(acc[nt], alf, b0, b1);
                        mma_f16(acc[nt], ahf,
                                blf[nt >> 1][(nt & 1) * 2 + 0],
                                blf[nt >> 1][(nt & 1) * 2 + 1]);
                    }
                }
                __syncthreads();
            }
        }

        // ---- fused pointwise: acc[nt = c*2 + gpair][rh*2 + gsub] ----
        {
            __half* whi = hsh + (size_t)t * BATCH * HID;
            __half* wlo = hsl + (size_t)t * BATCH * HID;
            float* outp = out ? out + (size_t)t * BATCH * HID : nullptr;
            const float* gxp = gx + (size_t)t * BATCH * G4H;
#pragma unroll
            for (int c = 0; c < 2; c++) {
                const int hl = (warp_n * 2 + c) * 4 + (lane & 3);   // local [0,16)
#pragma unroll
                for (int rh = 0; rh < 2; rh++) {
                    const int b = bm + warp_m * 16 + (lane >> 2) + rh * 8;
                    const size_t gb = (size_t)b * G4H + c0 + hl;
                    const float gi = gxp[gb]        + acc[c * 2 + 0][rh * 2 + 0];
                    const float gf = gxp[gb + 512]  + acc[c * 2 + 0][rh * 2 + 1];
                    const float gg = gxp[gb + 1024] + acc[c * 2 + 1][rh * 2 + 0];
                    const float go = gxp[gb + 1536] + acc[c * 2 + 1][rh * 2 + 1];
                    const int ci = c * 2 + rh;
                    const float cv = sigf(gf) * creg[ci] + sigf(gi) * tanhf(gg);
                    const float hv = sigf(go) * tanhf(cv);
                    creg[ci] = cv;
                    const size_t oidx = (size_t)b * HID + c0 + hl;
                    if (outp) outp[oidx] = hv;
                    const __half hh = __float2half(hv);
                    whi[oidx] = hh;
                    wlo[oidx] = __float2half(hv - __half2float(hh));
                }
            }
        }

        // ---- grid barrier (flag-based, cross-layer epochs) ----
        __syncthreads();
        if (tid == 0) {
            __threadfence();
            const unsigned old = atomicAdd(&d_gsync[0], 1u);
            if (old == phase * 128u + 127u) {
                atomicExch(&d_gsync[1], phase + 1u);
            } else {
                while (*((volatile unsigned*)&d_gsync[1]) <= phase) {}
            }
            __threadfence();
        }
        __syncthreads();
        phase++;
    }
}

// ---------------------------------------------------------------------------
// fp32 -> fp16 hi/lo split ([N,K] weights)
// ---------------------------------------------------------------------------
__global__ void split_k(const float* __restrict__ A,
                        __half* __restrict__ hi, __half* __restrict__ lo, long n)
{
    const long i = ((long)blockIdx.x * blockDim.x + threadIdx.x) * 4;
    if (i >= n) return;
    const float4 v = *reinterpret_cast<const float4*>(A + i);
    float a[4] = {v.x, v.y, v.z, v.w};
    __half h[4], l[4];
#pragma unroll
    for (int k = 0; k < 4; k++) {
        h[k] = __float2half(a[k]);
        l[k] = __float2half(a[k] - __half2float(h[k]));
    }
    *reinterpret_cast<uint2*>(hi + i) = *reinterpret_cast<uint2*>(h);
    *reinterpret_cast<uint2*>(lo + i) = *reinterpret_cast<uint2*>(l);
}

// transposing fp32 [K,N] -> fp16 hi/lo [N,K]
__global__ void splitT_k(const float* __restrict__ in,
                         __half* __restrict__ hi, __half* __restrict__ lo,
                         int K, int N)
{
    __shared__ float tile[32][33];
    int x = blockIdx.x * 32 + threadIdx.x;
    int y = blockIdx.y * 32 + threadIdx.y;
    if (x < N && y < K) tile[threadIdx.y][threadIdx.x] = in[(size_t)y * N + x];
    __syncthreads();
    const int n = blockIdx.x * 32 + threadIdx.y;
    const int k = blockIdx.y * 32 + threadIdx.x;
    if (n < N && k < K) {
        const float w = tile[threadIdx.x][threadIdx.y];
        const __half h = __float2half(w);
        hi[(size_t)n * K + k] = h;
        lo[(size_t)n * K + k] = __float2half(w - __half2float(h));
    }
}

// ---------------------------------------------------------------------------
// Adjacency contraction (fused residual blend + split in epilogue)
// ---------------------------------------------------------------------------
__launch_bounds__(256)
__global__ void adj_gemm(const float* __restrict__ adj, const float* __restrict__ T,
                         float* __restrict__ C, int relu,
                         const float* __restrict__ blend,
                         __half* __restrict__ ohi, __half* __restrict__ olo)
{
    constexpr int RB = 25;
    constexpr int N = BATCH * HID;
    __shared__ float as[RB][LSEQ];
    const int r0 = blockIdx.y * RB;
    const int n  = blockIdx.x * 256 + threadIdx.x;

    for (int i = threadIdx.x; i < RB * LSEQ; i += 256)
        as[i / LSEQ][i % LSEQ] = adj[(size_t)(r0 + i / LSEQ) * LSEQ + (i % LSEQ)];
    __syncthreads();

    float acc[RB];
#pragma unroll
    for (int r = 0; r < RB; r++) acc[r] = 0.0f;
    for (int k = 0; k < LSEQ; k++) {
        const float t = T[(size_t)k * N + n];
#pragma unroll
        for (int r = 0; r < RB; r++) acc[r] = fmaf(as[r][k], t, acc[r]);
    }
#pragma unroll
    for (int r = 0; r < RB; r++) {
        float v = acc[r];
        if (relu) v = fmaxf(v, 0.0f);
        const size_t idx = (size_t)(r0 + r) * N + n;
        if (blend) {
            const float m = (1.0f - SIGMA_MIX) * v + SIGMA_MIX * blend[idx];
            const __half h = __float2half(m);
            ohi[idx] = h;
            olo[idx] = __float2half(m - __half2float(h));
        } else {
            C[idx] = v;
        }
    }
}

// ---------------------------------------------------------------------------
// Embedding: emits qemb fp32 AND qa directly as fp16 hi/lo (no fp32 qa)
// ---------------------------------------------------------------------------
__global__ void embed_k(const int* __restrict__ q, const int* __restrict__ c,
                        const int* __restrict__ r, const int* __restrict__ qsh,
                        const int* __restrict__ csh, const int* __restrict__ rsh,
                        const float* __restrict__ Wq, const float* __restrict__ Wc,
                        const float* __restrict__ Wr,
                        __half* __restrict__ qah, __half* __restrict__ qal,
                        float* __restrict__ qemb)
{
    const long idx = (long)blockIdx.x * blockDim.x + threadIdx.x;
    if (idx >= (long)LSEQ * BATCH * HID) return;
    const int e = (int)(idx % HID);
    const int b = (int)((idx / HID) % BATCH);
    const int t = (int)(idx / ((long)HID * BATCH));
    const int pid = (t == 0) ? q[b * SEQ]  : qsh[b * SEQ + t - 1];
    const int cid = (t == 0) ? c[b * SEQ]  : csh[b * SEQ + t - 1];
    const int tgt = (t == 0) ? r[b * SEQ]  : rsh[b * SEQ + t - 1];
    const float qe = Wq[(size_t)pid * EMB + e] + Wc[(size_t)cid * EMB + e];
    qemb[idx] = qe;
    const float qav = qe + Wr[(size_t)tgt * EMB + e];
    const __half h = __float2half(qav);
    qah[idx] = h;
    qal[idx] = __float2half(qav - __half2float(h));
}

__global__ void bsum_k(const float* __restrict__ bih, const float* __restrict__ bhh,
                       float* __restrict__ bsum)
{
    const int i = blockIdx.x * blockDim.x + threadIdx.x;
    if (i < NLAY * G4H) bsum[i] = bih[i] + bhh[i];
}

// concat emitting fp16 hi/lo directly
__global__ void concat_half_k(const float* __restrict__ hg, const float* __restrict__ qe,
                              __half* __restrict__ hi, __half* __restrict__ lo)
{
    const long idx = (long)blockIdx.x * blockDim.x + threadIdx.x;
    if (idx >= (long)BATCH * SEQ * (2 * EMB)) return;
    const int f = (int)(idx % (2 * EMB));
    const int s = (int)((idx / (2 * EMB)) % SEQ);
    const int b = (int)(idx / ((long)(2 * EMB) * SEQ));
    const size_t src = ((size_t)(s + 1) * BATCH + b) * HID;
    const float v = (f < EMB) ? hg[src + f] : qe[src + (f - EMB)];
    const __half h = __float2half(v);
    hi[idx] = h;
    lo[idx] = __float2half(v - __half2float(h));
}

__global__ void mlp3_k(const float* __restrict__ X, const float* __restrict__ W3,
                       const float* __restrict__ b3, float* __restrict__ y, int M)
{
    const int warp = (blockIdx.x * blockDim.x + threadIdx.x) >> 5;
    const int lane = threadIdx.x & 31;
    if (warp >= M) return;
    const float* xr = X + (size_t)warp * NFC2;
    float s = 0.0f;
#pragma unroll
    for (int k = lane; k < NFC2; k += 32) s = fmaf(xr[k], W3[k], s);
#pragma unroll
    for (int o = 16; o > 0; o >>= 1) s += __shfl_down_sync(0xffffffffu, s, o);
    if (lane == 0) y[warp] = 1.0f / (1.0f + expf(-(s + b3[0])));
}

// ---------------------------------------------------------------------------
// Orchestration
// ---------------------------------------------------------------------------
extern "C" void kernel_launch(void* const* d_in, const int* in_sizes, int n_in,
                              void* d_out, int out_size)
{
    const int   *q   = (const int*)d_in[0],  *c   = (const int*)d_in[1];
    const int   *r   = (const int*)d_in[2],  *qsh = (const int*)d_in[3];
    const int   *csh = (const int*)d_in[4],  *rsh = (const int*)d_in[5];
    const float *adj = (const float*)d_in[6];
    const float *Wq  = (const float*)d_in[7], *Wc  = (const float*)d_in[8];
    const float *Wr  = (const float*)d_in[9];
    const float *Wih = (const float*)d_in[10], *Whh = (const float*)d_in[11];
    const float *bih = (const float*)d_in[12], *bhh = (const float*)d_in[13];
    const float *Wg  = (const float*)d_in[14];
    const float *W1  = (const float*)d_in[15], *b1 = (const float*)d_in[16];
    const float *W2  = (const float*)d_in[17], *b2 = (const float*)d_in[18];
    const float *W3  = (const float*)d_in[19], *b3 = (const float*)d_in[20];
    float* y = (float*)d_out;

    float *qemb, *x0, *gx, *t0, *g0, *m2, *bsum;
    unsigned* gsync;
    __half *ah, *al, *bh, *bl, *hsh, *hsl;
    cudaGetSymbolAddress((void**)&qemb, d_qemb);
    cudaGetSymbolAddress((void**)&x0,   d_x0);
    cudaGetSymbolAddress((void**)&gx,   d_gx);
    cudaGetSymbolAddress((void**)&t0,   d_t0);
    cudaGetSymbolAddress((void**)&g0,   d_g0);
    cudaGetSymbolAddress((void**)&m2,   d_m2);
    cudaGetSymbolAddress((void**)&bsum, d_bsum);
    cudaGetSymbolAddress((void**)&gsync, d_gsync);
    cudaGetSymbolAddress((void**)&ah,   d_ah);
    cudaGetSymbolAddress((void**)&al,   d_al);
    cudaGetSymbolAddress((void**)&bh,   d_bh);
    cudaGetSymbolAddress((void**)&bl,   d_bl);
    cudaGetSymbolAddress((void**)&hsh,  d_hsh);
    cudaGetSymbolAddress((void**)&hsl,  d_hsl);

    cudaFuncSetAttribute(mma_gemm, cudaFuncAttributeMaxDynamicSharedMemorySize, MMA_SMEM);
    cudaFuncSetAttribute(lstm_layer_mma, cudaFuncAttributeMaxDynamicSharedMemorySize, LSTM2_SMEM);

    const long NE = (long)LSEQ * BATCH * HID;

    // ---- prep (embed writes hseq hi/lo directly) ----
    bsum_k<<<(NLAY * G4H + 255) / 256, 256>>>(bih, bhh, bsum);
    embed_k<<<(unsigned)((NE + 255) / 256), 256>>>(q, c, r, qsh, csh, rsh,
                                                   Wq, Wc, Wr, hsh, hsl, qemb);
    cudaMemsetAsync(gsync, 0, 8, 0);

    // ---- 5-layer LSTM: hseq carries hi/lo activations across layers ----
    for (int l = 0; l < NLAY; l++) {
        split_k<<<(unsigned)((long)G4H * HID / 4 / 256), 256>>>(
            Wih + (size_t)l * G4H * HID, bh, bl, (long)G4H * HID);
        mma_gemm<<<dim3(G4H / 128, (LSEQ * BATCH) / 128), 256, MMA_SMEM>>>(
            hsh, hsl, bh, bl, gx, nullptr, nullptr, G4H, HID,
            bsum + (size_t)l * G4H, 0);
        lstm_layer_mma<<<128, 256, LSTM2_SMEM>>>(
            gx, Whh + (size_t)l * G4H * HID,
            (l == NLAY - 1) ? x0 : nullptr, hsh, hsl, (unsigned)(l * LSEQ));
    }
    const float* lstm_out = x0;

    // ---- 5 GCN layers (blend-split fused into adj_gemm epilogue) ----
    splitT_k<<<dim3(16, 16), dim3(32, 32)>>>(Wg, bh, bl, HID, HID);
    mma_gemm<<<dim3(HID / 128, (LSEQ * BATCH) / 128), 256, MMA_SMEM>>>(
        hsh, hsl, bh, bl, t0, nullptr, nullptr, HID, HID, nullptr, 0);
    adj_gemm<<<dim3((BATCH * HID) / 256, LSEQ / 25), 256>>>(
        adj, t0, nullptr, 1, lstm_out, ah, al);
    for (int i = 1; i < 5; i++) {
        splitT_k<<<dim3(16, 16), dim3(32, 32)>>>(Wg + (size_t)i * HID * HID, bh, bl,
                                                 HID, HID);
        mma_gemm<<<dim3(HID / 128, (LSEQ * BATCH) / 128), 256, MMA_SMEM>>>(
            ah, al, bh, bl, t0, nullptr, nullptr, HID, HID, nullptr, 0);
        if (i < 4) {
            adj_gemm<<<dim3((BATCH * HID) / 256, LSEQ / 25), 256>>>(
                adj, t0, nullptr, 1, lstm_out, ah, al);
        } else {
            adj_gemm<<<dim3((BATCH * HID) / 256, LSEQ / 25), 256>>>(
                adj, t0, g0, 0, nullptr, nullptr, nullptr);
        }
    }

    // ---- concat + MLP head (splits fused into producers) ----
    {
        const long n = (long)BATCH * SEQ * (2 * EMB);
        concat_half_k<<<(unsigned)((n + 255) / 256), 256>>>(g0, qemb, ah, al);
    }
    const int M = BATCH * SEQ;   // 50944 = 398*128
    splitT_k<<<dim3(16, 32), dim3(32, 32)>>>(W1, bh, bl, 2 * EMB, NFC1);
    mma_gemm<<<dim3(NFC1 / 128, M / 128), 256, MMA_SMEM>>>(
        ah, al, bh, bl, nullptr, hsh, hsl, NFC1, 2 * EMB, b1, 1);
    splitT_k<<<dim3(8, 16), dim3(32, 32)>>>(W2, bh, bl, NFC1, NFC2);
    mma_gemm<<<dim3(NFC2 / 128, M / 128), 256, MMA_SMEM>>>(
        hsh, hsl, bh, bl, m2, nullptr, nullptr, NFC2, NFC1, b2, 1);
    mlp3_k<<<(M * 32 + 255) / 256, 256>>>(m2, W3, b3, y, M);
}

// round 14
// speedup vs baseline: 1.0739x; 1.0210x over previous
#include <cuda_runtime.h>
#include <cuda_fp16.h>
#include <math.h>
#include <stdint.h>

#define BATCH 256
#define SEQ 199
#define LSEQ 200
#define EMB 512
#define HID 512
#define G4H 2048
#define NLAY 5
#define NFC1 512
#define NFC2 256
#define SIGMA_MIX 0.5f

#define SMEM_SWIZZLE_128B(b) ((b) ^ (((b) >> 3) & 0x70))

__device__ __forceinline__ uint32_t smem_to_u32(const void* p) {
    uint32_t a;
    asm("{ .reg .u64 t; cvta.to.shared.u64 t, %1; cvt.u32.u64 %0, t; }" : "=r"(a) : "l"(p));
    return a;
}
__device__ __forceinline__ void cp_async16(uint32_t saddr, const void* gaddr) {
    asm volatile("cp.async.cg.shared.global [%0], [%1], 16;" :: "r"(saddr), "l"(gaddr));
}
#define CP_COMMIT() asm volatile("cp.async.commit_group;" ::: "memory")
#define CP_WAIT(N)  asm volatile("cp.async.wait_group %0;" :: "n"(N) : "memory")

__device__ __forceinline__ void ldmatrix_x4(uint32_t* r, uint32_t addr) {
    asm volatile("ldmatrix.sync.aligned.m8n8.x4.shared.b16 {%0,%1,%2,%3}, [%4];"
                 : "=r"(r[0]), "=r"(r[1]), "=r"(r[2]), "=r"(r[3]) : "r"(addr));
}
__device__ __forceinline__ void mma_f16(float* d, const uint32_t* a, uint32_t b0, uint32_t b1) {
    asm volatile("mma.sync.aligned.m16n8k16.row.col.f32.f16.f16.f32 "
                 "{%0,%1,%2,%3}, {%4,%5,%6,%7}, {%8,%9}, {%0,%1,%2,%3};"
                 : "+f"(d[0]), "+f"(d[1]), "+f"(d[2]), "+f"(d[3])
                 : "r"(a[0]), "r"(a[1]), "r"(a[2]), "r"(a[3]), "r"(b0), "r"(b1));
}

// recurrence B smem addressing: row n = 1024B; XOR in-segment 16B chunk bits with n&7
__device__ __forceinline__ uint32_t baddr(int n, int kb) {
    return (uint32_t)(n * 1024 + (kb ^ ((n & 7) << 4)));
}

// ---------------------------------------------------------------------------
// Static device scratch
// ---------------------------------------------------------------------------
__device__ float d_qemb[(size_t)LSEQ*BATCH*HID];
__device__ float d_x0  [(size_t)LSEQ*BATCH*HID];
__device__ float d_gx  [(size_t)LSEQ*BATCH*G4H];
__device__ float d_t0  [(size_t)LSEQ*BATCH*HID];
__device__ float d_g0  [(size_t)LSEQ*BATCH*HID];
__device__ float d_m2  [(size_t)BATCH*SEQ*NFC2];
__device__ float d_bsum[(size_t)NLAY*G4H];
__device__ unsigned d_gsync[2];
__device__ __half d_ah  [(size_t)LSEQ*BATCH*1024];
__device__ __half d_al  [(size_t)LSEQ*BATCH*1024];
__device__ __half d_bh  [(size_t)G4H*HID];
__device__ __half d_bl  [(size_t)G4H*HID];
__device__ __half d_hsh [(size_t)LSEQ*BATCH*HID];
__device__ __half d_hsl [(size_t)LSEQ*BATCH*HID];

__device__ __forceinline__ float sigf(float x) { return 1.0f / (1.0f + expf(-x)); }

// ---------------------------------------------------------------------------
// fp16 fused-3-group NT GEMM, 2-blocks-per-SM version.
// Tile 128x128, BK=32. Stage = 32KB: A rows 128x128B (hi @byte 0-63, lo @64-127),
// B same at +16KB. 3 stages = 96KB -> 2 blocks/SM. SW128 conflict-free.
// Groups: Ahi*Bhi + Alo*Bhi + Ahi*Blo.
// ---------------------------------------------------------------------------
#define MMA_SMEM 98304

__global__ __launch_bounds__(256, 2)
void mma_gemm(const __half* __restrict__ Ahi, const __half* __restrict__ Alo,
              const __half* __restrict__ Bhi, const __half* __restrict__ Blo,
              float* __restrict__ C, __half* __restrict__ Chi, __half* __restrict__ Clo,
              int N, int K, const float* __restrict__ bias, int relu)
{
    extern __shared__ char smem[];
    const uint32_t smem_u = smem_to_u32(smem);
    const int tid = threadIdx.x;
    const int wid = tid >> 5, lane = tid & 31;
    const int warp_m = wid & 3, warp_n = wid >> 2;
    const long bm = (long)blockIdx.y * 128;
    const long bn = (long)blockIdx.x * 128;
    const int TI = K >> 5;               // 32-half k tiles

    float acc[2][8][4];
#pragma unroll
    for (int i = 0; i < 2; i++)
#pragma unroll
        for (int j = 0; j < 8; j++)
#pragma unroll
            for (int k = 0; k < 4; k++) acc[i][j][k] = 0.0f;

    // stage: A @0 (16KB), B @16384; hi = bytes [0,64) of each row, lo = [64,128)
    auto issue_load = [&](int stage, int kt) {
        const long k0 = (long)kt << 5;   // halves
        const uint32_t s0 = smem_u + stage * 32768;
#pragma unroll
        for (int c = 0; c < 8; c++) {
            const int cid = tid + c * 256;           // 0..2047
            const int mat = cid >> 10;               // 0=A, 1=B
            const int rem = cid & 1023;
            const int row = rem >> 3;
            const int o   = rem & 7;                 // byte col = o*16
            const int opnd = o >> 2;                 // 0=hi, 1=lo
            const int kch  = o & 3;
            const uint32_t sw = SMEM_SWIZZLE_128B((uint32_t)(row * 128 + o * 16));
            const __half* src = mat ? (opnd ? Blo : Bhi) : (opnd ? Alo : Ahi);
            const long base = mat ? bn : bm;
            cp_async16(s0 + mat * 16384 + sw,
                       src + (base + row) * (long)K + k0 + kch * 8);
        }
    };

    issue_load(0, 0); CP_COMMIT();
    issue_load(1, 1); CP_COMMIT();

    for (int j = 0; j < TI; j++) {
        if (j + 2 < TI)      { issue_load((j + 2) % 3, j + 2); CP_COMMIT(); CP_WAIT(2); }
        else if (j + 1 < TI) { CP_WAIT(1); }
        else                 { CP_WAIT(0); }
        __syncthreads();

        const uint32_t s0 = smem_u + (j % 3) * 32768;
#pragma unroll
        for (int ks = 0; ks < 2; ks++) {
            uint32_t afh[2][4], afl[2][4];
#pragma unroll
            for (int mt = 0; mt < 2; mt++) {
                const int row = warp_m * 32 + mt * 16 + (lane & 15);
                const int colb = ks * 32 + (lane >> 4) * 16;
                ldmatrix_x4(afh[mt], s0 + SMEM_SWIZZLE_128B((uint32_t)(row * 128 + colb)));
                ldmatrix_x4(afl[mt], s0 + SMEM_SWIZZLE_128B((uint32_t)(row * 128 + 64 + colb)));
            }
            uint32_t bfh[4][4], bfl[4][4];
#pragma unroll
            for (int nt2 = 0; nt2 < 4; nt2++) {
                const int nrow = warp_n * 64 + nt2 * 16 + ((lane >> 4) << 3) + (lane & 7);
                const int colb = ks * 32 + ((lane >> 3) & 1) * 16;
                ldmatrix_x4(bfh[nt2], s0 + 16384 + SMEM_SWIZZLE_128B((uint32_t)(nrow * 128 + colb)));
                ldmatrix_x4(bfl[nt2], s0 + 16384 + SMEM_SWIZZLE_128B((uint32_t)(nrow * 128 + 64 + colb)));
            }
#pragma unroll
            for (int mt = 0; mt < 2; mt++)
#pragma unroll
                for (int nt = 0; nt < 8; nt++) {
                    const uint32_t b0 = bfh[nt >> 1][(nt & 1) * 2 + 0];
                    const uint32_t b1 = bfh[nt >> 1][(nt & 1) * 2 + 1];
                    mma_f16(acc[mt][nt], afh[mt], b0, b1);
                    mma_f16(acc[mt][nt], afl[mt], b0, b1);
                    mma_f16(acc[mt][nt], afh[mt],
                            bfl[nt >> 1][(nt & 1) * 2 + 0],
                            bfl[nt >> 1][(nt & 1) * 2 + 1]);
                }
        }
        __syncthreads();
    }

#pragma unroll
    for (int mt = 0; mt < 2; mt++) {
        const long m0 = bm + warp_m * 32 + mt * 16 + (lane >> 2);
#pragma unroll
        for (int nt = 0; nt < 8; nt++) {
            const long nn = bn + warp_n * 64 + nt * 8 + (lane & 3) * 2;
            float bx = 0.0f, by = 0.0f;
            if (bias) { const float2 bv = *reinterpret_cast<const float2*>(&bias[nn]); bx = bv.x; by = bv.y; }
            float v0 = acc[mt][nt][0] + bx, v1 = acc[mt][nt][1] + by;
            float v2 = acc[mt][nt][2] + bx, v3 = acc[mt][nt][3] + by;
            if (relu) {
                v0 = fmaxf(v0, 0.0f); v1 = fmaxf(v1, 0.0f);
                v2 = fmaxf(v2, 0.0f); v3 = fmaxf(v3, 0.0f);
            }
            if (C) {
                *reinterpret_cast<float2*>(&C[m0 * (long)N + nn])       = make_float2(v0, v1);
                *reinterpret_cast<float2*>(&C[(m0 + 8) * (long)N + nn]) = make_float2(v2, v3);
            }
            if (Chi) {
                __half h0 = __float2half(v0), h1 = __float2half(v1);
                __half h2 = __float2half(v2), h3 = __float2half(v3);
                __half l0 = __float2half(v0 - __half2float(h0));
                __half l1 = __float2half(v1 - __half2float(h1));
                __half l2 = __float2half(v2 - __half2float(h2));
                __half l3 = __float2half(v3 - __half2float(h3));
                *reinterpret_cast<__half2*>(&Chi[m0 * (long)N + nn])       = __halves2half2(h0, h1);
                *reinterpret_cast<__half2*>(&Chi[(m0 + 8) * (long)N + nn]) = __halves2half2(h2, h3);
                *reinterpret_cast<__half2*>(&Clo[m0 * (long)N + nn])       = __halves2half2(l0, l1);
                *reinterpret_cast<__half2*>(&Clo[(m0 + 8) * (long)N + nn]) = __halves2half2(l2, l3);
            }
        }
    }
}

// ---------------------------------------------------------------------------
// Persistent tensor-core LSTM layer — 256 threads / 8 warps (unchanged)
// ---------------------------------------------------------------------------
#define LSTM2_SMEM 163840

__global__ __launch_bounds__(256)
void lstm_layer_mma(const float* __restrict__ gx, const float* __restrict__ Whh,
                    float* __restrict__ out,
                    __half* __restrict__ hsh, __half* __restrict__ hsl,
                    unsigned phase0)
{
    extern __shared__ char smem[];
    const uint32_t smem_u = smem_to_u32(smem);
    const uint32_t Ast_u = smem_u + 131072;

    const int tid = threadIdx.x;
    const int wid = tid >> 5, lane = tid & 31;
    const int warp_m = wid & 3;
    const int warp_n = wid >> 2;
    const int bm = (blockIdx.x & 3) * 64;
    const int c0 = (blockIdx.x >> 2) * 16;

    for (int i = tid; i < 64 * 512; i += 256) {
        const int n = i >> 9, k = i & 511;
        const int chunk = n >> 4, w16 = n & 15;
        const int gpair = w16 >> 3, rest = w16 & 7;
        const int hl = chunk * 4 + (rest >> 1);
        const int g  = gpair * 2 + (rest & 1);
        const float w = Whh[(size_t)(g * 512 + c0 + hl) * 512 + k];
        const __half h = __float2half(w);
        const __half l = __float2half(w - __half2float(h));
        const uint32_t off = baddr(n, k * 2);
        *reinterpret_cast<__half*>(smem + off) = h;
        *reinterpret_cast<__half*>(smem + 65536 + off) = l;
    }
    __syncthreads();

    float creg[4];
#pragma unroll
    for (int i = 0; i < 4; i++) creg[i] = 0.0f;
    unsigned phase = phase0;

    for (int t = 0; t < LSEQ; t++) {
        float acc[4][4];
#pragma unroll
        for (int i = 0; i < 4; i++)
#pragma unroll
            for (int j = 0; j < 4; j++) acc[i][j] = 0.0f;

        if (t > 0) {
            const __half* hhi = hsh + (size_t)(t - 1) * BATCH * HID;
            const __half* hlo = hsl + (size_t)(t - 1) * BATCH * HID;

            auto issueA = [&](int stage, int kc) {
                const uint32_t sa = Ast_u + stage * 16384;
#pragma unroll
                for (int c = 0; c < 2; c++) {
                    const int cid = tid + c * 256;
                    const int row = cid >> 3, o16 = cid & 7;
                    const uint32_t sw = SMEM_SWIZZLE_128B((uint32_t)(row * 128 + o16 * 16));
                    cp_async16(sa + sw,        hhi + (bm + row) * 512 + kc * 64 + o16 * 8);
                    cp_async16(sa + 8192 + sw, hlo + (bm + row) * 512 + kc * 64 + o16 * 8);
                }
            };
            issueA(0, 0);
            CP_COMMIT();
            for (int kc = 0; kc < 8; kc++) {
                if (kc < 7) { issueA((kc + 1) & 1, kc + 1); CP_COMMIT(); CP_WAIT(1); }
                else        { CP_WAIT(0); }
                __syncthreads();
                const uint32_t sa = Ast_u + (kc & 1) * 16384;
#pragma unroll
                for (int ks = 0; ks < 4; ks++) {
                    uint32_t ahf[4], alf[4];
                    {
                        const int row = warp_m * 16 + (lane & 15);
                        const int col = ks * 32 + (lane >> 4) * 16;
                        const uint32_t ad = sa + SMEM_SWIZZLE_128B((uint32_t)(row * 128 + col));
                        ldmatrix_x4(ahf, ad);
                        ldmatrix_x4(alf, ad + 8192);
                    }
                    uint32_t bhf[2][4], blf[2][4];
#pragma unroll
                    for (int g2 = 0; g2 < 2; g2++) {
                        const int n_r = warp_n * 32 + g2 * 16 + ((lane >> 4) << 3) + (lane & 7);
                        const int kb = (ks * 16 + ((lane >> 3) & 1) * 8) * 2 + kc * 128;
                        const uint32_t off = baddr(n_r, kb);
                        ldmatrix_x4(bhf[g2], smem_u + off);
                        ldmatrix_x4(blf[g2], smem_u + 65536 + off);
                    }
#pragma unroll
                    for (int nt = 0; nt < 4; nt++) {
                        const uint32_t b0 = bhf[nt >> 1][(nt & 1) * 2 + 0];
                        const uint32_t b1 = bhf[nt >> 1][(nt & 1) * 2 + 1];
                        mma_f16(acc[nt], ahf, b0, b1);
                        mma_f16(acc[nt], alf, b0, b1);
                        mma_f16(acc[nt], ahf,
                                blf[nt >> 1][(nt & 1) * 2 + 0],
                                blf[nt >> 1][(nt & 1) * 2 + 1]);
                    }
                }
                __syncthreads();
            }
        }

        {
            __half* whi = hsh + (size_t)t * BATCH * HID;
            __half* wlo = hsl + (size_t)t * BATCH * HID;
            float* outp = out ? out + (size_t)t * BATCH * HID : nullptr;
            const float* gxp = gx + (size_t)t * BATCH * G4H;
#pragma unroll
            for (int c = 0; c < 2; c++) {
                const int hl = (warp_n * 2 + c) * 4 + (lane & 3);
#pragma unroll
                for (int rh = 0; rh < 2; rh++) {
                    const int b = bm + warp_m * 16 + (lane >> 2) + rh * 8;
                    const size_t gb = (size_t)b * G4H + c0 + hl;
                    const float gi = gxp[gb]        + acc[c * 2 + 0][rh * 2 + 0];
                    const float gf = gxp[gb + 512]  + acc[c * 2 + 0][rh * 2 + 1];
                    const float gg = gxp[gb + 1024] + acc[c * 2 + 1][rh * 2 + 0];
                    const float go = gxp[gb + 1536] + acc[c * 2 + 1][rh * 2 + 1];
                    const int ci = c * 2 + rh;
                    const float cv = sigf(gf) * creg[ci] + sigf(gi) * tanhf(gg);
                    const float hv = sigf(go) * tanhf(cv);
                    creg[ci] = cv;
                    const size_t oidx = (size_t)b * HID + c0 + hl;
                    if (outp) outp[oidx] = hv;
                    const __half hh = __float2half(hv);
                    whi[oidx] = hh;
                    wlo[oidx] = __float2half(hv - __half2float(hh));
                }
            }
        }

        __syncthreads();
        if (tid == 0) {
            __threadfence();
            const unsigned old = atomicAdd(&d_gsync[0], 1u);
            if (old == phase * 128u + 127u) {
                atomicExch(&d_gsync[1], phase + 1u);
            } else {
                while (*((volatile unsigned*)&d_gsync[1]) <= phase) {}
            }
            __threadfence();
        }
        __syncthreads();
        phase++;
    }
}

// ---------------------------------------------------------------------------
// fp32 -> fp16 hi/lo split ([N,K] weights)
// ---------------------------------------------------------------------------
__global__ void split_k(const float* __restrict__ A,
                        __half* __restrict__ hi, __half* __restrict__ lo, long n)
{
    const long i = ((long)blockIdx.x * blockDim.x + threadIdx.x) * 4;
    if (i >= n) return;
    const float4 v = *reinterpret_cast<const float4*>(A + i);
    float a[4] = {v.x, v.y, v.z, v.w};
    __half h[4], l[4];
#pragma unroll
    for (int k = 0; k < 4; k++) {
        h[k] = __float2half(a[k]);
        l[k] = __float2half(a[k] - __half2float(h[k]));
    }
    *reinterpret_cast<uint2*>(hi + i) = *reinterpret_cast<uint2*>(h);
    *reinterpret_cast<uint2*>(lo + i) = *reinterpret_cast<uint2*>(l);
}

// transposing fp32 [K,N] -> fp16 hi/lo [N,K]
__global__ void splitT_k(const float* __restrict__ in,
                         __half* __restrict__ hi, __half* __restrict__ lo,
                         int K, int N)
{
    __shared__ float tile[32][33];
    int x = blockIdx.x * 32 + threadIdx.x;
    int y = blockIdx.y * 32 + threadIdx.y;
    if (x < N && y < K) tile[threadIdx.y][threadIdx.x] = in[(size_t)y * N + x];
    __syncthreads();
    const int n = blockIdx.x * 32 + threadIdx.y;
    const int k = blockIdx.y * 32 + threadIdx.x;
    if (n < N && k < K) {
        const float w = tile[threadIdx.x][threadIdx.y];
        const __half h = __float2half(w);
        hi[(size_t)n * K + k] = h;
        lo[(size_t)n * K + k] = __float2half(w - __half2float(h));
    }
}

// ---------------------------------------------------------------------------
// Adjacency contraction (fused residual blend + split in epilogue)
// ---------------------------------------------------------------------------
__launch_bounds__(256)
__global__ void adj_gemm(const float* __restrict__ adj, const float* __restrict__ T,
                         float* __restrict__ C, int relu,
                         const float* __restrict__ blend,
                         __half* __restrict__ ohi, __half* __restrict__ olo)
{
    constexpr int RB = 25;
    constexpr int N = BATCH * HID;
    __shared__ float as[RB][LSEQ];
    const int r0 = blockIdx.y * RB;
    const int n  = blockIdx.x * 256 + threadIdx.x;

    for (int i = threadIdx.x; i < RB * LSEQ; i += 256)
        as[i / LSEQ][i % LSEQ] = adj[(size_t)(r0 + i / LSEQ) * LSEQ + (i % LSEQ)];
    __syncthreads();

    float acc[RB];
#pragma unroll
    for (int r = 0; r < RB; r++) acc[r] = 0.0f;
    for (int k = 0; k < LSEQ; k++) {
        const float t = T[(size_t)k * N + n];
#pragma unroll
        for (int r = 0; r < RB; r++) acc[r] = fmaf(as[r][k], t, acc[r]);
    }
#pragma unroll
    for (int r = 0; r < RB; r++) {
        float v = acc[r];
        if (relu) v = fmaxf(v, 0.0f);
        const size_t idx = (size_t)(r0 + r) * N + n;
        if (blend) {
            const float m = (1.0f - SIGMA_MIX) * v + SIGMA_MIX * blend[idx];
            const __half h = __float2half(m);
            ohi[idx] = h;
            olo[idx] = __float2half(m - __half2float(h));
        } else {
            C[idx] = v;
        }
    }
}

// ---------------------------------------------------------------------------
// Embedding: emits qemb fp32 AND qa directly as fp16 hi/lo
// ---------------------------------------------------------------------------
__global__ void embed_k(const int* __restrict__ q, const int* __restrict__ c,
                        const int* __restrict__ r, const int* __restrict__ qsh,
                        const int* __restrict__ csh, const int* __restrict__ rsh,
                        const float* __restrict__ Wq, const float* __restrict__ Wc,
                        const float* __restrict__ Wr,
                        __half* __restrict__ qah, __half* __restrict__ qal,
                        float* __restrict__ qemb)
{
    const long idx = (long)blockIdx.x * blockDim.x + threadIdx.x;
    if (idx >= (long)LSEQ * BATCH * HID) return;
    const int e = (int)(idx % HID);
    const int b = (int)((idx / HID) % BATCH);
    const int t = (int)(idx / ((long)HID * BATCH));
    const int pid = (t == 0) ? q[b * SEQ]  : qsh[b * SEQ + t - 1];
    const int cid = (t == 0) ? c[b * SEQ]  : csh[b * SEQ + t - 1];
    const int tgt = (t == 0) ? r[b * SEQ]  : rsh[b * SEQ + t - 1];
    const float qe = Wq[(size_t)pid * EMB + e] + Wc[(size_t)cid * EMB + e];
    qemb[idx] = qe;
    const float qav = qe + Wr[(size_t)tgt * EMB + e];
    const __half h = __float2half(qav);
    qah[idx] = h;
    qal[idx] = __float2half(qav - __half2float(h));
}

__global__ void bsum_k(const float* __restrict__ bih, const float* __restrict__ bhh,
                       float* __restrict__ bsum)
{
    const int i = blockIdx.x * blockDim.x + threadIdx.x;
    if (i < NLAY * G4H) bsum[i] = bih[i] + bhh[i];
}

__global__ void concat_half_k(const float* __restrict__ hg, const float* __restrict__ qe,
                              __half* __restrict__ hi, __half* __restrict__ lo)
{
    const long idx = (long)blockIdx.x * blockDim.x + threadIdx.x;
    if (idx >= (long)BATCH * SEQ * (2 * EMB)) return;
    const int f = (int)(idx % (2 * EMB));
    const int s = (int)((idx / (2 * EMB)) % SEQ);
    const int b = (int)(idx / ((long)(2 * EMB) * SEQ));
    const size_t src = ((size_t)(s + 1) * BATCH + b) * HID;
    const float v = (f < EMB) ? hg[src + f] : qe[src + (f - EMB)];
    const __half h = __float2half(v);
    hi[idx] = h;
    lo[idx] = __float2half(v - __half2float(h));
}

__global__ void mlp3_k(const float* __restrict__ X, const float* __restrict__ W3,
                       const float* __restrict__ b3, float* __restrict__ y, int M)
{
    const int warp = (blockIdx.x * blockDim.x + threadIdx.x) >> 5;
    const int lane = threadIdx.x & 31;
    if (warp >= M) return;
    const float* xr = X + (size_t)warp * NFC2;
    float s = 0.0f;
#pragma unroll
    for (int k = lane; k < NFC2; k += 32) s = fmaf(xr[k], W3[k], s);
#pragma unroll
    for (int o = 16; o > 0; o >>= 1) s += __shfl_down_sync(0xffffffffu, s, o);
    if (lane == 0) y[warp] = 1.0f / (1.0f + expf(-(s + b3[0])));
}

// ---------------------------------------------------------------------------
// Orchestration
// ---------------------------------------------------------------------------
extern "C" void kernel_launch(void* const* d_in, const int* in_sizes, int n_in,
                              void* d_out, int out_size)
{
    const int   *q   = (const int*)d_in[0],  *c   = (const int*)d_in[1];
    const int   *r   = (const int*)d_in[2],  *qsh = (const int*)d_in[3];
    const int   *csh = (const int*)d_in[4],  *rsh = (const int*)d_in[5];
    const float *adj = (const float*)d_in[6];
    const float *Wq  = (const float*)d_in[7], *Wc  = (const float*)d_in[8];
    const float *Wr  = (const float*)d_in[9];
    const float *Wih = (const float*)d_in[10], *Whh = (const float*)d_in[11];
    const float *bih = (const float*)d_in[12], *bhh = (const float*)d_in[13];
    const float *Wg  = (const float*)d_in[14];
    const float *W1  = (const float*)d_in[15], *b1 = (const float*)d_in[16];
    const float *W2  = (const float*)d_in[17], *b2 = (const float*)d_in[18];
    const float *W3  = (const float*)d_in[19], *b3 = (const float*)d_in[20];
    float* y = (float*)d_out;

    float *qemb, *x0, *gx, *t0, *g0, *m2, *bsum;
    unsigned* gsync;
    __half *ah, *al, *bh, *bl, *hsh, *hsl;
    cudaGetSymbolAddress((void**)&qemb, d_qemb);
    cudaGetSymbolAddress((void**)&x0,   d_x0);
    cudaGetSymbolAddress((void**)&gx,   d_gx);
    cudaGetSymbolAddress((void**)&t0,   d_t0);
    cudaGetSymbolAddress((void**)&g0,   d_g0);
    cudaGetSymbolAddress((void**)&m2,   d_m2);
    cudaGetSymbolAddress((void**)&bsum, d_bsum);
    cudaGetSymbolAddress((void**)&gsync, d_gsync);
    cudaGetSymbolAddress((void**)&ah,   d_ah);
    cudaGetSymbolAddress((void**)&al,   d_al);
    cudaGetSymbolAddress((void**)&bh,   d_bh);
    cudaGetSymbolAddress((void**)&bl,   d_bl);
    cudaGetSymbolAddress((void**)&hsh,  d_hsh);
    cudaGetSymbolAddress((void**)&hsl,  d_hsl);

    cudaFuncSetAttribute(mma_gemm, cudaFuncAttributeMaxDynamicSharedMemorySize, MMA_SMEM);
    cudaFuncSetAttribute(lstm_layer_mma, cudaFuncAttributeMaxDynamicSharedMemorySize, LSTM2_SMEM);

    const long NE = (long)LSEQ * BATCH * HID;

    // ---- prep ----
    bsum_k<<<(NLAY * G4H + 255) / 256, 256>>>(bih, bhh, bsum);
    embed_k<<<(unsigned)((NE + 255) / 256), 256>>>(q, c, r, qsh, csh, rsh,
                                                   Wq, Wc, Wr, hsh, hsl, qemb);
    cudaMemsetAsync(gsync, 0, 8, 0);

    // ---- 5-layer LSTM ----
    for (int l = 0; l < NLAY; l++) {
        split_k<<<(unsigned)((long)G4H * HID / 4 / 256), 256>>>(
            Wih + (size_t)l * G4H * HID, bh, bl, (long)G4H * HID);
        mma_gemm<<<dim3(G4H / 128, (LSEQ * BATCH) / 128), 256, MMA_SMEM>>>(
            hsh, hsl, bh, bl, gx, nullptr, nullptr, G4H, HID,
            bsum + (size_t)l * G4H, 0);
        lstm_layer_mma<<<128, 256, LSTM2_SMEM>>>(
            gx, Whh + (size_t)l * G4H * HID,
            (l == NLAY - 1) ? x0 : nullptr, hsh, hsl, (unsigned)(l * LSEQ));
    }
    const float* lstm_out = x0;

    // ---- 5 GCN layers ----
    splitT_k<<<dim3(16, 16), dim3(32, 32)>>>(Wg, bh, bl, HID, HID);
    mma_gemm<<<dim3(HID / 128, (LSEQ * BATCH) / 128), 256, MMA_SMEM>>>(
        hsh, hsl, bh, bl, t0, nullptr, nullptr, HID, HID, nullptr, 0);
    adj_gemm<<<dim3((BATCH * HID) / 256, LSEQ / 25), 256>>>(
        adj, t0, nullptr, 1, lstm_out, ah, al);
    for (int i = 1; i < 5; i++) {
        splitT_k<<<dim3(16, 16), dim3(32, 32)>>>(Wg + (size_t)i * HID * HID, bh, bl,
                                                 HID, HID);
        mma_gemm<<<dim3(HID / 128, (LSEQ * BATCH) / 128), 256, MMA_SMEM>>>(
            ah, al, bh, bl, t0, nullptr, nullptr, HID, HID, nullptr, 0);
        if (i < 4) {
            adj_gemm<<<dim3((BATCH * HID) / 256, LSEQ / 25), 256>>>(
                adj, t0, nullptr, 1, lstm_out, ah, al);
        } else {
            adj_gemm<<<dim3((BATCH * HID) / 256, LSEQ / 25), 256>>>(
                adj, t0, g0, 0, nullptr, nullptr, nullptr);
        }
    }

    // ---- concat + MLP head ----
    {
        const long n = (long)BATCH * SEQ * (2 * EMB);
        concat_half_k<<<(unsigned)((n + 255) / 256), 256>>>(g0, qemb, ah, al);
    }
    const int M = BATCH * SEQ;   // 50944 = 398*128
    splitT_k<<<dim3(16, 32), dim3(32, 32)>>>(W1, bh, bl, 2 * EMB, NFC1);
    mma_gemm<<<dim3(NFC1 / 128, M / 128), 256, MMA_SMEM>>>(
        ah, al, bh, bl, nullptr, hsh, hsl, NFC1, 2 * EMB, b1, 1);
    splitT_k<<<dim3(8, 16), dim3(32, 32)>>>(W2, bh, bl, NFC1, NFC2);
    mma_gemm<<<dim3(NFC2 / 128, M / 128), 256, MMA_SMEM>>>(
        hsh, hsl, bh, bl, m2, nullptr, nullptr, NFC2, NFC1, b2, 1);
    mlp3_k<<<(M * 32 + 255) / 256, 256>>>(m2, W3, b3, y, M);
}

// round 15
// speedup vs baseline: 1.0743x; 1.0003x over previous
#include <cuda_runtime.h>
#include <cuda_fp16.h>
#include <math.h>
#include <stdint.h>

#define BATCH 256
#define SEQ 199
#define LSEQ 200
#define EMB 512
#define HID 512
#define G4H 2048
#define NLAY 5
#define NFC1 512
#define NFC2 256
#define SIGMA_MIX 0.5f

#define SMEM_SWIZZLE_128B(b) ((b) ^ (((b) >> 3) & 0x70))

__device__ __forceinline__ uint32_t smem_to_u32(const void* p) {
    uint32_t a;
    asm("{ .reg .u64 t; cvta.to.shared.u64 t, %1; cvt.u32.u64 %0, t; }" : "=r"(a) : "l"(p));
    return a;
}
__device__ __forceinline__ void cp_async16(uint32_t saddr, const void* gaddr) {
    asm volatile("cp.async.cg.shared.global [%0], [%1], 16;" :: "r"(saddr), "l"(gaddr));
}
#define CP_COMMIT() asm volatile("cp.async.commit_group;" ::: "memory")
#define CP_WAIT(N)  asm volatile("cp.async.wait_group %0;" :: "n"(N) : "memory")

__device__ __forceinline__ void ldmatrix_x4(uint32_t* r, uint32_t addr) {
    asm volatile("ldmatrix.sync.aligned.m8n8.x4.shared.b16 {%0,%1,%2,%3}, [%4];"
                 : "=r"(r[0]), "=r"(r[1]), "=r"(r[2]), "=r"(r[3]) : "r"(addr));
}
__device__ __forceinline__ void mma_f16(float* d, const uint32_t* a, uint32_t b0, uint32_t b1) {
    asm volatile("mma.sync.aligned.m16n8k16.row.col.f32.f16.f16.f32 "
                 "{%0,%1,%2,%3}, {%4,%5,%6,%7}, {%8,%9}, {%0,%1,%2,%3};"
                 : "+f"(d[0]), "+f"(d[1]), "+f"(d[2]), "+f"(d[3])
                 : "r"(a[0]), "r"(a[1]), "r"(a[2]), "r"(a[3]), "r"(b0), "r"(b1));
}

// recurrence B smem addressing: row n = 1024B; XOR in-segment 16B chunk bits with n&7
__device__ __forceinline__ uint32_t baddr(int n, int kb) {
    return (uint32_t)(n * 1024 + (kb ^ ((n & 7) << 4)));
}

// ---------------------------------------------------------------------------
// Static device scratch
// ---------------------------------------------------------------------------
__device__ float d_qemb[(size_t)LSEQ*BATCH*HID];
__device__ float d_gx  [(size_t)LSEQ*BATCH*G4H];
__device__ float d_t0  [(size_t)LSEQ*BATCH*HID];
__device__ float d_g0  [(size_t)LSEQ*BATCH*HID];
__device__ float d_m2  [(size_t)BATCH*SEQ*NFC2];
__device__ float d_bsum[(size_t)NLAY*G4H];
__device__ unsigned d_gsync[2];
__device__ __half d_ah  [(size_t)LSEQ*BATCH*1024];
__device__ __half d_al  [(size_t)LSEQ*BATCH*1024];
__device__ __half d_bh  [(size_t)G4H*HID];
__device__ __half d_bl  [(size_t)G4H*HID];
__device__ __half d_hsh [(size_t)LSEQ*BATCH*HID];
__device__ __half d_hsl [(size_t)LSEQ*BATCH*HID];

__device__ __forceinline__ float sigf(float x) { return 1.0f / (1.0f + expf(-x)); }

// ---------------------------------------------------------------------------
// fp16 fused-3-group NT GEMM, 2-blocks-per-SM (unchanged from R14 — passing).
// ---------------------------------------------------------------------------
#define MMA_SMEM 98304

__global__ __launch_bounds__(256, 2)
void mma_gemm(const __half* __restrict__ Ahi, const __half* __restrict__ Alo,
              const __half* __restrict__ Bhi, const __half* __restrict__ Blo,
              float* __restrict__ C, __half* __restrict__ Chi, __half* __restrict__ Clo,
              int N, int K, const float* __restrict__ bias, int relu)
{
    extern __shared__ char smem[];
    const uint32_t smem_u = smem_to_u32(smem);
    const int tid = threadIdx.x;
    const int wid = tid >> 5, lane = tid & 31;
    const int warp_m = wid & 3, warp_n = wid >> 2;
    const long bm = (long)blockIdx.y * 128;
    const long bn = (long)blockIdx.x * 128;
    const int TI = K >> 5;

    float acc[2][8][4];
#pragma unroll
    for (int i = 0; i < 2; i++)
#pragma unroll
        for (int j = 0; j < 8; j++)
#pragma unroll
            for (int k = 0; k < 4; k++) acc[i][j][k] = 0.0f;

    auto issue_load = [&](int stage, int kt) {
        const long k0 = (long)kt << 5;
        const uint32_t s0 = smem_u + stage * 32768;
#pragma unroll
        for (int c = 0; c < 8; c++) {
            const int cid = tid + c * 256;
            const int mat = cid >> 10;
            const int rem = cid & 1023;
            const int row = rem >> 3;
            const int o   = rem & 7;
            const int opnd = o >> 2;
            const int kch  = o & 3;
            const uint32_t sw = SMEM_SWIZZLE_128B((uint32_t)(row * 128 + o * 16));
            const __half* src = mat ? (opnd ? Blo : Bhi) : (opnd ? Alo : Ahi);
            const long base = mat ? bn : bm;
            cp_async16(s0 + mat * 16384 + sw,
                       src + (base + row) * (long)K + k0 + kch * 8);
        }
    };

    issue_load(0, 0); CP_COMMIT();
    issue_load(1, 1); CP_COMMIT();

    for (int j = 0; j < TI; j++) {
        if (j + 2 < TI)      { issue_load((j + 2) % 3, j + 2); CP_COMMIT(); CP_WAIT(2); }
        else if (j + 1 < TI) { CP_WAIT(1); }
        else                 { CP_WAIT(0); }
        __syncthreads();

        const uint32_t s0 = smem_u + (j % 3) * 32768;
#pragma unroll
        for (int ks = 0; ks < 2; ks++) {
            uint32_t afh[2][4], afl[2][4];
#pragma unroll
            for (int mt = 0; mt < 2; mt++) {
                const int row = warp_m * 32 + mt * 16 + (lane & 15);
                const int colb = ks * 32 + (lane >> 4) * 16;
                ldmatrix_x4(afh[mt], s0 + SMEM_SWIZZLE_128B((uint32_t)(row * 128 + colb)));
                ldmatrix_x4(afl[mt], s0 + SMEM_SWIZZLE_128B((uint32_t)(row * 128 + 64 + colb)));
            }
            uint32_t bfh[4][4], bfl[4][4];
#pragma unroll
            for (int nt2 = 0; nt2 < 4; nt2++) {
                const int nrow = warp_n * 64 + nt2 * 16 + ((lane >> 4) << 3) + (lane & 7);
                const int colb = ks * 32 + ((lane >> 3) & 1) * 16;
                ldmatrix_x4(bfh[nt2], s0 + 16384 + SMEM_SWIZZLE_128B((uint32_t)(nrow * 128 + colb)));
                ldmatrix_x4(bfl[nt2], s0 + 16384 + SMEM_SWIZZLE_128B((uint32_t)(nrow * 128 + 64 + colb)));
            }
#pragma unroll
            for (int mt = 0; mt < 2; mt++)
#pragma unroll
                for (int nt = 0; nt < 8; nt++) {
                    const uint32_t b0 = bfh[nt >> 1][(nt & 1) * 2 + 0];
                    const uint32_t b1 = bfh[nt >> 1][(nt & 1) * 2 + 1];
                    mma_f16(acc[mt][nt], afh[mt], b0, b1);
                    mma_f16(acc[mt][nt], afl[mt], b0, b1);
                    mma_f16(acc[mt][nt], afh[mt],
                            bfl[nt >> 1][(nt & 1) * 2 + 0],
                            bfl[nt >> 1][(nt & 1) * 2 + 1]);
                }
        }
        __syncthreads();
    }

#pragma unroll
    for (int mt = 0; mt < 2; mt++) {
        const long m0 = bm + warp_m * 32 + mt * 16 + (lane >> 2);
#pragma unroll
        for (int nt = 0; nt < 8; nt++) {
            const long nn = bn + warp_n * 64 + nt * 8 + (lane & 3) * 2;
            float bx = 0.0f, by = 0.0f;
            if (bias) { const float2 bv = *reinterpret_cast<const float2*>(&bias[nn]); bx = bv.x; by = bv.y; }
            float v0 = acc[mt][nt][0] + bx, v1 = acc[mt][nt][1] + by;
            float v2 = acc[mt][nt][2] + bx, v3 = acc[mt][nt][3] + by;
            if (relu) {
                v0 = fmaxf(v0, 0.0f); v1 = fmaxf(v1, 0.0f);
                v2 = fmaxf(v2, 0.0f); v3 = fmaxf(v3, 0.0f);
            }
            if (C) {
                *reinterpret_cast<float2*>(&C[m0 * (long)N + nn])       = make_float2(v0, v1);
                *reinterpret_cast<float2*>(&C[(m0 + 8) * (long)N + nn]) = make_float2(v2, v3);
            }
            if (Chi) {
                __half h0 = __float2half(v0), h1 = __float2half(v1);
                __half h2 = __float2half(v2), h3 = __float2half(v3);
                __half l0 = __float2half(v0 - __half2float(h0));
                __half l1 = __float2half(v1 - __half2float(h1));
                __half l2 = __float2half(v2 - __half2float(h2));
                __half l3 = __float2half(v3 - __half2float(h3));
                *reinterpret_cast<__half2*>(&Chi[m0 * (long)N + nn])       = __halves2half2(h0, h1);
                *reinterpret_cast<__half2*>(&Chi[(m0 + 8) * (long)N + nn]) = __halves2half2(h2, h3);
                *reinterpret_cast<__half2*>(&Clo[m0 * (long)N + nn])       = __halves2half2(l0, l1);
                *reinterpret_cast<__half2*>(&Clo[(m0 + 8) * (long)N + nn]) = __halves2half2(l2, l3);
            }
        }
    }
}

// ---------------------------------------------------------------------------
// Persistent tensor-core LSTM layer — 4 K-chunks of 128 halves, 3-stage ring.
// smem: Whh hi 64KB @0, lo 64KB @65536; A stages @131072, 3 x 32KB.
// A stage: sub0 hi @0, sub0 lo @8192, sub1 hi @16384, sub1 lo @24576.
// 8 syncthreads/step (was 16).
// ---------------------------------------------------------------------------
#define LSTM2_SMEM 229376

__global__ __launch_bounds__(256)
void lstm_layer_mma(const float* __restrict__ gx, const float* __restrict__ Whh,
                    __half* __restrict__ hsh, __half* __restrict__ hsl,
                    unsigned phase0)
{
    extern __shared__ char smem[];
    const uint32_t smem_u = smem_to_u32(smem);
    const uint32_t Ast_u = smem_u + 131072;

    const int tid = threadIdx.x;
    const int wid = tid >> 5, lane = tid & 31;
    const int warp_m = wid & 3;
    const int warp_n = wid >> 2;
    const int bm = (blockIdx.x & 3) * 64;
    const int c0 = (blockIdx.x >> 2) * 16;

    for (int i = tid; i < 64 * 512; i += 256) {
        const int n = i >> 9, k = i & 511;
        const int chunk = n >> 4, w16 = n & 15;
        const int gpair = w16 >> 3, rest = w16 & 7;
        const int hl = chunk * 4 + (rest >> 1);
        const int g  = gpair * 2 + (rest & 1);
        const float w = Whh[(size_t)(g * 512 + c0 + hl) * 512 + k];
        const __half h = __float2half(w);
        const __half l = __float2half(w - __half2float(h));
        const uint32_t off = baddr(n, k * 2);
        *reinterpret_cast<__half*>(smem + off) = h;
        *reinterpret_cast<__half*>(smem + 65536 + off) = l;
    }
    __syncthreads();

    float creg[4];
#pragma unroll
    for (int i = 0; i < 4; i++) creg[i] = 0.0f;
    unsigned phase = phase0;

    for (int t = 0; t < LSEQ; t++) {
        float acc[4][4];
#pragma unroll
        for (int i = 0; i < 4; i++)
#pragma unroll
            for (int j = 0; j < 4; j++) acc[i][j] = 0.0f;

        if (t > 0) {
            const __half* hhi = hsh + (size_t)(t - 1) * BATCH * HID;
            const __half* hlo = hsl + (size_t)(t - 1) * BATCH * HID;

            // load one 128-half chunk (32KB: 2 subs x (hi 8KB + lo 8KB))
            auto issueA = [&](int stage, int kc) {
                const uint32_t sa = Ast_u + stage * 32768;
#pragma unroll
                for (int c = 0; c < 8; c++) {
                    const int cid = tid + c * 256;       // 0..2047
                    const int sub = cid >> 10;
                    const int plane = (cid >> 9) & 1;    // 0=hi,1=lo
                    const int rr = cid & 511;
                    const int row = rr >> 3, o16 = rr & 7;
                    const uint32_t sw = SMEM_SWIZZLE_128B((uint32_t)(row * 128 + o16 * 16));
                    const __half* src = plane ? hlo : hhi;
                    cp_async16(sa + sub * 16384 + plane * 8192 + sw,
                               src + (bm + row) * 512 + kc * 128 + sub * 64 + o16 * 8);
                }
            };
            issueA(0, 0); CP_COMMIT();
            issueA(1, 1); CP_COMMIT();
            for (int kc = 0; kc < 4; kc++) {
                if (kc + 2 < 4)      { issueA((kc + 2) % 3, kc + 2); CP_COMMIT(); CP_WAIT(2); }
                else if (kc + 1 < 4) { CP_WAIT(1); }
                else                 { CP_WAIT(0); }
                __syncthreads();
                const uint32_t sa = Ast_u + (kc % 3) * 32768;
#pragma unroll
                for (int ks = 0; ks < 8; ks++) {
                    const int sub = ks >> 2, ksl = ks & 3;
                    uint32_t ahf[4], alf[4];
                    {
                        const int row = warp_m * 16 + (lane & 15);
                        const int col = ksl * 32 + (lane >> 4) * 16;
                        const uint32_t ad = sa + sub * 16384
                                          + SMEM_SWIZZLE_128B((uint32_t)(row * 128 + col));
                        ldmatrix_x4(ahf, ad);
                        ldmatrix_x4(alf, ad + 8192);
                    }
                    uint32_t bhf[2][4], blf[2][4];
#pragma unroll
                    for (int g2 = 0; g2 < 2; g2++) {
                        const int n_r = warp_n * 32 + g2 * 16 + ((lane >> 4) << 3) + (lane & 7);
                        const int khalf = kc * 128 + ks * 16 + ((lane >> 3) & 1) * 8;
                        const uint32_t off = baddr(n_r, khalf * 2);
                        ldmatrix_x4(bhf[g2], smem_u + off);
                        ldmatrix_x4(blf[g2], smem_u + 65536 + off);
                    }
#pragma unroll
                    for (int nt = 0; nt < 4; nt++) {
                        const uint32_t b0 = bhf[nt >> 1][(nt & 1) * 2 + 0];
                        const uint32_t b1 = bhf[nt >> 1][(nt & 1) * 2 + 1];
                        mma_f16(acc[nt], ahf, b0, b1);
                        mma_f16(acc[nt], alf, b0, b1);
                        mma_f16(acc[nt], ahf,
                                blf[nt >> 1][(nt & 1) * 2 + 0],
                                blf[nt >> 1][(nt & 1) * 2 + 1]);
                    }
                }
                __syncthreads();
            }
        }

        {
            __half* whi = hsh + (size_t)t * BATCH * HID;
            __half* wlo = hsl + (size_t)t * BATCH * HID;
            const float* gxp = gx + (size_t)t * BATCH * G4H;
#pragma unroll
            for (int c = 0; c < 2; c++) {
                const int hl = (warp_n * 2 + c) * 4 + (lane & 3);
#pragma unroll
                for (int rh = 0; rh < 2; rh++) {
                    const int b = bm + warp_m * 16 + (lane >> 2) + rh * 8;
                    const size_t gb = (size_t)b * G4H + c0 + hl;
                    const float gi = gxp[gb]        + acc[c * 2 + 0][rh * 2 + 0];
                    const float gf = gxp[gb + 512]  + acc[c * 2 + 0][rh * 2 + 1];
                    const float gg = gxp[gb + 1024] + acc[c * 2 + 1][rh * 2 + 0];
                    const float go = gxp[gb + 1536] + acc[c * 2 + 1][rh * 2 + 1];
                    const int ci = c * 2 + rh;
                    const float cv = sigf(gf) * creg[ci] + sigf(gi) * tanhf(gg);
                    const float hv = sigf(go) * tanhf(cv);
                    creg[ci] = cv;
                    const size_t oidx = (size_t)b * HID + c0 + hl;
                    const __half hh = __float2half(hv);
                    whi[oidx] = hh;
                    wlo[oidx] = __float2half(hv - __half2float(hh));
                }
            }
        }

        __syncthreads();
        if (tid == 0) {
            __threadfence();
            const unsigned old = atomicAdd(&d_gsync[0], 1u);
            if (old == phase * 128u + 127u) {
                atomicExch(&d_gsync[1], phase + 1u);
            } else {
                while (*((volatile unsigned*)&d_gsync[1]) <= phase) {}
            }
            __threadfence();
        }
        __syncthreads();
        phase++;
    }
}

// ---------------------------------------------------------------------------
// fp32 -> fp16 hi/lo split ([N,K] weights)
// ---------------------------------------------------------------------------
__global__ void split_k(const float* __restrict__ A,
                        __half* __restrict__ hi, __half* __restrict__ lo, long n)
{
    const long i = ((long)blockIdx.x * blockDim.x + threadIdx.x) * 4;
    if (i >= n) return;
    const float4 v = *reinterpret_cast<const float4*>(A + i);
    float a[4] = {v.x, v.y, v.z, v.w};
    __half h[4], l[4];
#pragma unroll
    for (int k = 0; k < 4; k++) {
        h[k] = __float2half(a[k]);
        l[k] = __float2half(a[k] - __half2float(h[k]));
    }
    *reinterpret_cast<uint2*>(hi + i) = *reinterpret_cast<uint2*>(h);
    *reinterpret_cast<uint2*>(lo + i) = *reinterpret_cast<uint2*>(l);
}

// transposing fp32 [K,N] -> fp16 hi/lo [N,K]
__global__ void splitT_k(const float* __restrict__ in,
                         __half* __restrict__ hi, __half* __restrict__ lo,
                         int K, int N)
{
    __shared__ float tile[32][33];
    int x = blockIdx.x * 32 + threadIdx.x;
    int y = blockIdx.y * 32 + threadIdx.y;
    if (x < N && y < K) tile[threadIdx.y][threadIdx.x] = in[(size_t)y * N + x];
    __syncthreads();
    const int n = blockIdx.x * 32 + threadIdx.y;
    const int k = blockIdx.y * 32 + threadIdx.x;
    if (n < N && k < K) {
        const float w = tile[threadIdx.x][threadIdx.y];
        const __half h = __float2half(w);
        hi[(size_t)n * K + k] = h;
        lo[(size_t)n * K + k] = __float2half(w - __half2float(h));
    }
}

// ---------------------------------------------------------------------------
// Adjacency contraction, RB=50. blend given as fp16 hi/lo pair (lstm h).
// ---------------------------------------------------------------------------
__launch_bounds__(256)
__global__ void adj_gemm(const float* __restrict__ adj, const float* __restrict__ T,
                         float* __restrict__ C, int relu,
                         const __half* __restrict__ bhi, const __half* __restrict__ blo,
                         __half* __restrict__ ohi, __half* __restrict__ olo)
{
    constexpr int RB = 50;
    constexpr int N = BATCH * HID;
    __shared__ float as[RB][LSEQ];
    const int r0 = blockIdx.y * RB;
    const int n  = blockIdx.x * 256 + threadIdx.x;

    for (int i = threadIdx.x; i < RB * LSEQ; i += 256)
        as[i / LSEQ][i % LSEQ] = adj[(size_t)(r0 + i / LSEQ) * LSEQ + (i % LSEQ)];
    __syncthreads();

    float acc[RB];
#pragma unroll
    for (int r = 0; r < RB; r++) acc[r] = 0.0f;
    for (int k = 0; k < LSEQ; k++) {
        const float t = T[(size_t)k * N + n];
#pragma unroll
        for (int r = 0; r < RB; r++) acc[r] = fmaf(as[r][k], t, acc[r]);
    }
#pragma unroll
    for (int r = 0; r < RB; r++) {
        float v = acc[r];
        if (relu) v = fmaxf(v, 0.0f);
        const size_t idx = (size_t)(r0 + r) * N + n;
        if (bhi) {
            const float bl = __half2float(bhi[idx]) + __half2float(blo[idx]);
            const float m = (1.0f - SIGMA_MIX) * v + SIGMA_MIX * bl;
            const __half h = __float2half(m);
            ohi[idx] = h;
            olo[idx] = __float2half(m - __half2float(h));
        } else {
            C[idx] = v;
        }
    }
}

// ---------------------------------------------------------------------------
// Embedding: emits qemb fp32 AND qa directly as fp16 hi/lo
// ---------------------------------------------------------------------------
__global__ void embed_k(const int* __restrict__ q, const int* __restrict__ c,
                        const int* __restrict__ r, const int* __restrict__ qsh,
                        const int* __restrict__ csh, const int* __restrict__ rsh,
                        const float* __restrict__ Wq, const float* __restrict__ Wc,
                        const float* __restrict__ Wr,
                        __half* __restrict__ qah, __half* __restrict__ qal,
                        float* __restrict__ qemb)
{
    const long idx = (long)blockIdx.x * blockDim.x + threadIdx.x;
    if (idx >= (long)LSEQ * BATCH * HID) return;
    const int e = (int)(idx % HID);
    const int b = (int)((idx / HID) % BATCH);
    const int t = (int)(idx / ((long)HID * BATCH));
    const int pid = (t == 0) ? q[b * SEQ]  : qsh[b * SEQ + t - 1];
    const int cid = (t == 0) ? c[b * SEQ]  : csh[b * SEQ + t - 1];
    const int tgt = (t == 0) ? r[b * SEQ]  : rsh[b * SEQ + t - 1];
    const float qe = Wq[(size_t)pid * EMB + e] + Wc[(size_t)cid * EMB + e];
    qemb[idx] = qe;
    const float qav = qe + Wr[(size_t)tgt * EMB + e];
    const __half h = __float2half(qav);
    qah[idx] = h;
    qal[idx] = __float2half(qav - __half2float(h));
}

__global__ void bsum_k(const float* __restrict__ bih, const float* __restrict__ bhh,
                       float* __restrict__ bsum)
{
    const int i = blockIdx.x * blockDim.x + threadIdx.x;
    if (i < NLAY * G4H) bsum[i] = bih[i] + bhh[i];
}

__global__ void concat_half_k(const float* __restrict__ hg, const float* __restrict__ qe,
                              __half* __restrict__ hi, __half* __restrict__ lo)
{
    const long idx = (long)blockIdx.x * blockDim.x + threadIdx.x;
    if (idx >= (long)BATCH * SEQ * (2 * EMB)) return;
    const int f = (int)(idx % (2 * EMB));
    const int s = (int)((idx / (2 * EMB)) % SEQ);
    const int b = (int)(idx / ((long)(2 * EMB) * SEQ));
    const size_t src = ((size_t)(s + 1) * BATCH + b) * HID;
    const float v = (f < EMB) ? hg[src + f] : qe[src + (f - EMB)];
    const __half h = __float2half(v);
    hi[idx] = h;
    lo[idx] = __float2half(v - __half2float(h));
}

__global__ void mlp3_k(const float* __restrict__ X, const float* __restrict__ W3,
                       const float* __restrict__ b3, float* __restrict__ y, int M)
{
    const int warp = (blockIdx.x * blockDim.x + threadIdx.x) >> 5;
    const int lane = threadIdx.x & 31;
    if (warp >= M) return;
    const float* xr = X + (size_t)warp * NFC2;
    float s = 0.0f;
#pragma unroll
    for (int k = lane; k < NFC2; k += 32) s = fmaf(xr[k], W3[k], s);
#pragma unroll
    for (int o = 16; o > 0; o >>= 1) s += __shfl_down_sync(0xffffffffu, s, o);
    if (lane == 0) y[warp] = 1.0f / (1.0f + expf(-(s + b3[0])));
}

// ---------------------------------------------------------------------------
// Orchestration
// ---------------------------------------------------------------------------
extern "C" void kernel_launch(void* const* d_in, const int* in_sizes, int n_in,
                              void* d_out, int out_size)
{
    const int   *q   = (const int*)d_in[0],  *c   = (const int*)d_in[1];
    const int   *r   = (const int*)d_in[2],  *qsh = (const int*)d_in[3];
    const int   *csh = (const int*)d_in[4],  *rsh = (const int*)d_in[5];
    const float *adj = (const float*)d_in[6];
    const float *Wq  = (const float*)d_in[7], *Wc  = (const float*)d_in[8];
    const float *Wr  = (const float*)d_in[9];
    const float *Wih = (const float*)d_in[10], *Whh = (const float*)d_in[11];
    const float *bih = (const float*)d_in[12], *bhh = (const float*)d_in[13];
    const float *Wg  = (const float*)d_in[14];
    const float *W1  = (const float*)d_in[15], *b1 = (const float*)d_in[16];
    const float *W2  = (const float*)d_in[17], *b2 = (const float*)d_in[18];
    const float *W3  = (const float*)d_in[19], *b3 = (const float*)d_in[20];
    float* y = (float*)d_out;

    float *qemb, *gx, *t0, *g0, *m2, *bsum;
    unsigned* gsync;
    __half *ah, *al, *bh, *bl, *hsh, *hsl;
    cudaGetSymbolAddress((void**)&qemb, d_qemb);
    cudaGetSymbolAddress((void**)&gx,   d_gx);
    cudaGetSymbolAddress((void**)&t0,   d_t0);
    cudaGetSymbolAddress((void**)&g0,   d_g0);
    cudaGetSymbolAddress((void**)&m2,   d_m2);
    cudaGetSymbolAddress((void**)&bsum, d_bsum);
    cudaGetSymbolAddress((void**)&gsync, d_gsync);
    cudaGetSymbolAddress((void**)&ah,   d_ah);
    cudaGetSymbolAddress((void**)&al,   d_al);
    cudaGetSymbolAddress((void**)&bh,   d_bh);
    cudaGetSymbolAddress((void**)&bl,   d_bl);
    cudaGetSymbolAddress((void**)&hsh,  d_hsh);
    cudaGetSymbolAddress((void**)&hsl,  d_hsl);

    cudaFuncSetAttribute(mma_gemm, cudaFuncAttributeMaxDynamicSharedMemorySize, MMA_SMEM);
    cudaFuncSetAttribute(lstm_layer_mma, cudaFuncAttributeMaxDynamicSharedMemorySize, LSTM2_SMEM);

    const long NE = (long)LSEQ * BATCH * HID;

    // ---- prep ----
    bsum_k<<<(NLAY * G4H + 255) / 256, 256>>>(bih, bhh, bsum);
    embed_k<<<(unsigned)((NE + 255) / 256), 256>>>(q, c, r, qsh, csh, rsh,
                                                   Wq, Wc, Wr, hsh, hsl, qemb);
    cudaMemsetAsync(gsync, 0, 8, 0);

    // ---- 5-layer LSTM ----
    for (int l = 0; l < NLAY; l++) {
        split_k<<<(unsigned)((long)G4H * HID / 4 / 256), 256>>>(
            Wih + (size_t)l * G4H * HID, bh, bl, (long)G4H * HID);
        mma_gemm<<<dim3(G4H / 128, (LSEQ * BATCH) / 128), 256, MMA_SMEM>>>(
            hsh, hsl, bh, bl, gx, nullptr, nullptr, G4H, HID,
            bsum + (size_t)l * G4H, 0);
        lstm_layer_mma<<<128, 256, LSTM2_SMEM>>>(
            gx, Whh + (size_t)l * G4H * HID, hsh, hsl, (unsigned)(l * LSEQ));
    }

    // ---- 5 GCN layers (blend = hsh/hsl of last LSTM layer) ----
    splitT_k<<<dim3(16, 16), dim3(32, 32)>>>(Wg, bh, bl, HID, HID);
    mma_gemm<<<dim3(HID / 128, (LSEQ * BATCH) / 128), 256, MMA_SMEM>>>(
        hsh, hsl, bh, bl, t0, nullptr, nullptr, HID, HID, nullptr, 0);
    adj_gemm<<<dim3((BATCH * HID) / 256, LSEQ / 50), 256>>>(
        adj, t0, nullptr, 1, hsh, hsl, ah, al);
    for (int i = 1; i < 5; i++) {
        splitT_k<<<dim3(16, 16), dim3(32, 32)>>>(Wg + (size_t)i * HID * HID, bh, bl,
                                                 HID, HID);
        mma_gemm<<<dim3(HID / 128, (LSEQ * BATCH) / 128), 256, MMA_SMEM>>>(
            ah, al, bh, bl, t0, nullptr, nullptr, HID, HID, nullptr, 0);
        if (i < 4) {
            adj_gemm<<<dim3((BATCH * HID) / 256, LSEQ / 50), 256>>>(
                adj, t0, nullptr, 1, hsh, hsl, ah, al);
        } else {
            adj_gemm<<<dim3((BATCH * HID) / 256, LSEQ / 50), 256>>>(
                adj, t0, g0, 0, nullptr, nullptr, nullptr, nullptr);
        }
    }

    // ---- concat + MLP head ----
    {
        const long n = (long)BATCH * SEQ * (2 * EMB);
        concat_half_k<<<(unsigned)((n + 255) / 256), 256>>>(g0, qemb, ah, al);
    }
    const int M = BATCH * SEQ;   // 50944 = 398*128
    splitT_k<<<dim3(16, 32), dim3(32, 32)>>>(W1, bh, bl, 2 * EMB, NFC1);
    mma_gemm<<<dim3(NFC1 / 128, M / 128), 256, MMA_SMEM>>>(
        ah, al, bh, bl, nullptr, hsh, hsl, NFC1, 2 * EMB, b1, 1);
    splitT_k<<<dim3(8, 16), dim3(32, 32)>>>(W2, bh, bl, NFC1, NFC2);
    mma_gemm<<<dim3(NFC2 / 128, M / 128), 256, MMA_SMEM>>>(
        hsh, hsl, bh, bl, m2, nullptr, nullptr, NFC2, NFC1, b2, 1);
    mlp3_k<<<(M * 32 + 255) / 256, 256>>>(m2, W3, b3, y, M);
}

// round 16
// speedup vs baseline: 1.1295x; 1.0515x over previous
#include <cuda_runtime.h>
#include <cuda_fp16.h>
#include <math.h>
#include <stdint.h>

#define BATCH 256
#define SEQ 199
#define LSEQ 200
#define EMB 512
#define HID 512
#define G4H 2048
#define NLAY 5
#define NFC1 512
#define NFC2 256
#define SIGMA_MIX 0.5f

#define SMEM_SWIZZLE_128B(b) ((b) ^ (((b) >> 3) & 0x70))

__device__ __forceinline__ uint32_t smem_to_u32(const void* p) {
    uint32_t a;
    asm("{ .reg .u64 t; cvta.to.shared.u64 t, %1; cvt.u32.u64 %0, t; }" : "=r"(a) : "l"(p));
    return a;
}
__device__ __forceinline__ void cp_async16(uint32_t saddr, const void* gaddr) {
    asm volatile("cp.async.cg.shared.global [%0], [%1], 16;" :: "r"(saddr), "l"(gaddr));
}
#define CP_COMMIT() asm volatile("cp.async.commit_group;" ::: "memory")
#define CP_WAIT(N)  asm volatile("cp.async.wait_group %0;" :: "n"(N) : "memory")

__device__ __forceinline__ void ldmatrix_x4(uint32_t* r, uint32_t addr) {
    asm volatile("ldmatrix.sync.aligned.m8n8.x4.shared.b16 {%0,%1,%2,%3}, [%4];"
                 : "=r"(r[0]), "=r"(r[1]), "=r"(r[2]), "=r"(r[3]) : "r"(addr));
}
__device__ __forceinline__ void mma_f16(float* d, const uint32_t* a, uint32_t b0, uint32_t b1) {
    asm volatile("mma.sync.aligned.m16n8k16.row.col.f32.f16.f16.f32 "
                 "{%0,%1,%2,%3}, {%4,%5,%6,%7}, {%8,%9}, {%0,%1,%2,%3};"
                 : "+f"(d[0]), "+f"(d[1]), "+f"(d[2]), "+f"(d[3])
                 : "r"(a[0]), "r"(a[1]), "r"(a[2]), "r"(a[3]), "r"(b0), "r"(b1));
}

// recurrence B smem addressing: row n = 1024B; XOR in-segment 16B chunk bits with n&7
__device__ __forceinline__ uint32_t baddr(int n, int kb) {
    return (uint32_t)(n * 1024 + (kb ^ ((n & 7) << 4)));
}

// hardware tanh approximation (sm_75+): 1 MUFU op, rel err ~1e-5
__device__ __forceinline__ float tanh_ap(float x) {
    float y;
    asm("tanh.approx.f32 %0, %1;" : "=f"(y) : "f"(x));
    return y;
}
__device__ __forceinline__ float sig_ap(float x) {
    return fmaf(0.5f, tanh_ap(0.5f * x), 0.5f);
}

// ---------------------------------------------------------------------------
// Static device scratch
// ---------------------------------------------------------------------------
__device__ float d_qemb[(size_t)LSEQ*BATCH*HID];
__device__ float d_gx  [(size_t)LSEQ*BATCH*G4H];
__device__ float d_t0  [(size_t)LSEQ*BATCH*HID];
__device__ float d_g0  [(size_t)LSEQ*BATCH*HID];
__device__ float d_m2  [(size_t)BATCH*SEQ*NFC2];
__device__ float d_bsum[(size_t)NLAY*G4H];
__device__ unsigned d_gsync[2];
__device__ __half d_ah  [(size_t)LSEQ*BATCH*1024];
__device__ __half d_al  [(size_t)LSEQ*BATCH*1024];
__device__ __half d_bh  [(size_t)G4H*HID];
__device__ __half d_bl  [(size_t)G4H*HID];
__device__ __half d_hsh [(size_t)LSEQ*BATCH*HID];
__device__ __half d_hsl [(size_t)LSEQ*BATCH*HID];

__device__ __forceinline__ float sigf(float x) { return 1.0f / (1.0f + expf(-x)); }

// ---------------------------------------------------------------------------
// fp16 fused-3-group NT GEMM, 2-blocks-per-SM (unchanged — passing).
// ---------------------------------------------------------------------------
#define MMA_SMEM 98304

__global__ __launch_bounds__(256, 2)
void mma_gemm(const __half* __restrict__ Ahi, const __half* __restrict__ Alo,
              const __half* __restrict__ Bhi, const __half* __restrict__ Blo,
              float* __restrict__ C, __half* __restrict__ Chi, __half* __restrict__ Clo,
              int N, int K, const float* __restrict__ bias, int relu)
{
    extern __shared__ char smem[];
    const uint32_t smem_u = smem_to_u32(smem);
    const int tid = threadIdx.x;
    const int wid = tid >> 5, lane = tid & 31;
    const int warp_m = wid & 3, warp_n = wid >> 2;
    const long bm = (long)blockIdx.y * 128;
    const long bn = (long)blockIdx.x * 128;
    const int TI = K >> 5;

    float acc[2][8][4];
#pragma unroll
    for (int i = 0; i < 2; i++)
#pragma unroll
        for (int j = 0; j < 8; j++)
#pragma unroll
            for (int k = 0; k < 4; k++) acc[i][j][k] = 0.0f;

    auto issue_load = [&](int stage, int kt) {
        const long k0 = (long)kt << 5;
        const uint32_t s0 = smem_u + stage * 32768;
#pragma unroll
        for (int c = 0; c < 8; c++) {
            const int cid = tid + c * 256;
            const int mat = cid >> 10;
            const int rem = cid & 1023;
            const int row = rem >> 3;
            const int o   = rem & 7;
            const int opnd = o >> 2;
            const int kch  = o & 3;
            const uint32_t sw = SMEM_SWIZZLE_128B((uint32_t)(row * 128 + o * 16));
            const __half* src = mat ? (opnd ? Blo : Bhi) : (opnd ? Alo : Ahi);
            const long base = mat ? bn : bm;
            cp_async16(s0 + mat * 16384 + sw,
                       src + (base + row) * (long)K + k0 + kch * 8);
        }
    };

    issue_load(0, 0); CP_COMMIT();
    issue_load(1, 1); CP_COMMIT();

    for (int j = 0; j < TI; j++) {
        if (j + 2 < TI)      { issue_load((j + 2) % 3, j + 2); CP_COMMIT(); CP_WAIT(2); }
        else if (j + 1 < TI) { CP_WAIT(1); }
        else                 { CP_WAIT(0); }
        __syncthreads();

        const uint32_t s0 = smem_u + (j % 3) * 32768;
#pragma unroll
        for (int ks = 0; ks < 2; ks++) {
            uint32_t afh[2][4], afl[2][4];
#pragma unroll
            for (int mt = 0; mt < 2; mt++) {
                const int row = warp_m * 32 + mt * 16 + (lane & 15);
                const int colb = ks * 32 + (lane >> 4) * 16;
                ldmatrix_x4(afh[mt], s0 + SMEM_SWIZZLE_128B((uint32_t)(row * 128 + colb)));
                ldmatrix_x4(afl[mt], s0 + SMEM_SWIZZLE_128B((uint32_t)(row * 128 + 64 + colb)));
            }
            uint32_t bfh[4][4], bfl[4][4];
#pragma unroll
            for (int nt2 = 0; nt2 < 4; nt2++) {
                const int nrow = warp_n * 64 + nt2 * 16 + ((lane >> 4) << 3) + (lane & 7);
                const int colb = ks * 32 + ((lane >> 3) & 1) * 16;
                ldmatrix_x4(bfh[nt2], s0 + 16384 + SMEM_SWIZZLE_128B((uint32_t)(nrow * 128 + colb)));
                ldmatrix_x4(bfl[nt2], s0 + 16384 + SMEM_SWIZZLE_128B((uint32_t)(nrow * 128 + 64 + colb)));
            }
#pragma unroll
            for (int mt = 0; mt < 2; mt++)
#pragma unroll
                for (int nt = 0; nt < 8; nt++) {
                    const uint32_t b0 = bfh[nt >> 1][(nt & 1) * 2 + 0];
                    const uint32_t b1 = bfh[nt >> 1][(nt & 1) * 2 + 1];
                    mma_f16(acc[mt][nt], afh[mt], b0, b1);
                    mma_f16(acc[mt][nt], afl[mt], b0, b1);
                    mma_f16(acc[mt][nt], afh[mt],
                            bfl[nt >> 1][(nt & 1) * 2 + 0],
                            bfl[nt >> 1][(nt & 1) * 2 + 1]);
                }
        }
        __syncthreads();
    }

#pragma unroll
    for (int mt = 0; mt < 2; mt++) {
        const long m0 = bm + warp_m * 32 + mt * 16 + (lane >> 2);
#pragma unroll
        for (int nt = 0; nt < 8; nt++) {
            const long nn = bn + warp_n * 64 + nt * 8 + (lane & 3) * 2;
            float bx = 0.0f, by = 0.0f;
            if (bias) { const float2 bv = *reinterpret_cast<const float2*>(&bias[nn]); bx = bv.x; by = bv.y; }
            float v0 = acc[mt][nt][0] + bx, v1 = acc[mt][nt][1] + by;
            float v2 = acc[mt][nt][2] + bx, v3 = acc[mt][nt][3] + by;
            if (relu) {
                v0 = fmaxf(v0, 0.0f); v1 = fmaxf(v1, 0.0f);
                v2 = fmaxf(v2, 0.0f); v3 = fmaxf(v3, 0.0f);
            }
            if (C) {
                *reinterpret_cast<float2*>(&C[m0 * (long)N + nn])       = make_float2(v0, v1);
                *reinterpret_cast<float2*>(&C[(m0 + 8) * (long)N + nn]) = make_float2(v2, v3);
            }
            if (Chi) {
                __half h0 = __float2half(v0), h1 = __float2half(v1);
                __half h2 = __float2half(v2), h3 = __float2half(v3);
                __half l0 = __float2half(v0 - __half2float(h0));
                __half l1 = __float2half(v1 - __half2float(h1));
                __half l2 = __float2half(v2 - __half2float(h2));
                __half l3 = __float2half(v3 - __half2float(h3));
                *reinterpret_cast<__half2*>(&Chi[m0 * (long)N + nn])       = __halves2half2(h0, h1);
                *reinterpret_cast<__half2*>(&Chi[(m0 + 8) * (long)N + nn]) = __halves2half2(h2, h3);
                *reinterpret_cast<__half2*>(&Clo[m0 * (long)N + nn])       = __halves2half2(l0, l1);
                *reinterpret_cast<__half2*>(&Clo[(m0 + 8) * (long)N + nn]) = __halves2half2(l2, l3);
            }
        }
    }
}

// ---------------------------------------------------------------------------
// Persistent tensor-core LSTM layer (R15 structure; pointwise now MUFU-lean)
// ---------------------------------------------------------------------------
#define LSTM2_SMEM 229376

__global__ __launch_bounds__(256)
void lstm_layer_mma(const float* __restrict__ gx, const float* __restrict__ Whh,
                    __half* __restrict__ hsh, __half* __restrict__ hsl,
                    unsigned phase0)
{
    extern __shared__ char smem[];
    const uint32_t smem_u = smem_to_u32(smem);
    const uint32_t Ast_u = smem_u + 131072;

    const int tid = threadIdx.x;
    const int wid = tid >> 5, lane = tid & 31;
    const int warp_m = wid & 3;
    const int warp_n = wid >> 2;
    const int bm = (blockIdx.x & 3) * 64;
    const int c0 = (blockIdx.x >> 2) * 16;

    for (int i = tid; i < 64 * 512; i += 256) {
        const int n = i >> 9, k = i & 511;
        const int chunk = n >> 4, w16 = n & 15;
        const int gpair = w16 >> 3, rest = w16 & 7;
        const int hl = chunk * 4 + (rest >> 1);
        const int g  = gpair * 2 + (rest & 1);
        const float w = Whh[(size_t)(g * 512 + c0 + hl) * 512 + k];
        const __half h = __float2half(w);
        const __half l = __float2half(w - __half2float(h));
        const uint32_t off = baddr(n, k * 2);
        *reinterpret_cast<__half*>(smem + off) = h;
        *reinterpret_cast<__half*>(smem + 65536 + off) = l;
    }
    __syncthreads();

    float creg[4];
#pragma unroll
    for (int i = 0; i < 4; i++) creg[i] = 0.0f;
    unsigned phase = phase0;

    for (int t = 0; t < LSEQ; t++) {
        float acc[4][4];
#pragma unroll
        for (int i = 0; i < 4; i++)
#pragma unroll
            for (int j = 0; j < 4; j++) acc[i][j] = 0.0f;

        if (t > 0) {
            const __half* hhi = hsh + (size_t)(t - 1) * BATCH * HID;
            const __half* hlo = hsl + (size_t)(t - 1) * BATCH * HID;

            auto issueA = [&](int stage, int kc) {
                const uint32_t sa = Ast_u + stage * 32768;
#pragma unroll
                for (int c = 0; c < 8; c++) {
                    const int cid = tid + c * 256;
                    const int sub = cid >> 10;
                    const int plane = (cid >> 9) & 1;
                    const int rr = cid & 511;
                    const int row = rr >> 3, o16 = rr & 7;
                    const uint32_t sw = SMEM_SWIZZLE_128B((uint32_t)(row * 128 + o16 * 16));
                    const __half* src = plane ? hlo : hhi;
                    cp_async16(sa + sub * 16384 + plane * 8192 + sw,
                               src + (bm + row) * 512 + kc * 128 + sub * 64 + o16 * 8);
                }
            };
            issueA(0, 0); CP_COMMIT();
            issueA(1, 1); CP_COMMIT();
            for (int kc = 0; kc < 4; kc++) {
                if (kc + 2 < 4)      { issueA((kc + 2) % 3, kc + 2); CP_COMMIT(); CP_WAIT(2); }
                else if (kc + 1 < 4) { CP_WAIT(1); }
                else                 { CP_WAIT(0); }
                __syncthreads();
                const uint32_t sa = Ast_u + (kc % 3) * 32768;
#pragma unroll
                for (int ks = 0; ks < 8; ks++) {
                    const int sub = ks >> 2, ksl = ks & 3;
                    uint32_t ahf[4], alf[4];
                    {
                        const int row = warp_m * 16 + (lane & 15);
                        const int col = ksl * 32 + (lane >> 4) * 16;
                        const uint32_t ad = sa + sub * 16384
                                          + SMEM_SWIZZLE_128B((uint32_t)(row * 128 + col));
                        ldmatrix_x4(ahf, ad);
                        ldmatrix_x4(alf, ad + 8192);
                    }
                    uint32_t bhf[2][4], blf[2][4];
#pragma unroll
                    for (int g2 = 0; g2 < 2; g2++) {
                        const int n_r = warp_n * 32 + g2 * 16 + ((lane >> 4) << 3) + (lane & 7);
                        const int khalf = kc * 128 + ks * 16 + ((lane >> 3) & 1) * 8;
                        const uint32_t off = baddr(n_r, khalf * 2);
                        ldmatrix_x4(bhf[g2], smem_u + off);
                        ldmatrix_x4(blf[g2], smem_u + 65536 + off);
                    }
#pragma unroll
                    for (int nt = 0; nt < 4; nt++) {
                        const uint32_t b0 = bhf[nt >> 1][(nt & 1) * 2 + 0];
                        const uint32_t b1 = bhf[nt >> 1][(nt & 1) * 2 + 1];
                        mma_f16(acc[nt], ahf, b0, b1);
                        mma_f16(acc[nt], alf, b0, b1);
                        mma_f16(acc[nt], ahf,
                                blf[nt >> 1][(nt & 1) * 2 + 0],
                                blf[nt >> 1][(nt & 1) * 2 + 1]);
                    }
                }
                __syncthreads();
            }
        }

        // ---- fused pointwise: hardware tanh.approx for all nonlinearities ----
        {
            __half* whi = hsh + (size_t)t * BATCH * HID;
            __half* wlo = hsl + (size_t)t * BATCH * HID;
            const float* gxp = gx + (size_t)t * BATCH * G4H;
#pragma unroll
            for (int c = 0; c < 2; c++) {
                const int hl = (warp_n * 2 + c) * 4 + (lane & 3);
#pragma unroll
                for (int rh = 0; rh < 2; rh++) {
                    const int b = bm + warp_m * 16 + (lane >> 2) + rh * 8;
                    const size_t gb = (size_t)b * G4H + c0 + hl;
                    const float gi = gxp[gb]        + acc[c * 2 + 0][rh * 2 + 0];
                    const float gf = gxp[gb + 512]  + acc[c * 2 + 0][rh * 2 + 1];
                    const float gg = gxp[gb + 1024] + acc[c * 2 + 1][rh * 2 + 0];
                    const float go = gxp[gb + 1536] + acc[c * 2 + 1][rh * 2 + 1];
                    const int ci = c * 2 + rh;
                    const float cv = sig_ap(gf) * creg[ci] + sig_ap(gi) * tanh_ap(gg);
                    const float hv = sig_ap(go) * tanh_ap(cv);
                    creg[ci] = cv;
                    const size_t oidx = (size_t)b * HID + c0 + hl;
                    const __half hh = __float2half(hv);
                    whi[oidx] = hh;
                    wlo[oidx] = __float2half(hv - __half2float(hh));
                }
            }
        }

        __syncthreads();
        if (tid == 0) {
            __threadfence();
            const unsigned old = atomicAdd(&d_gsync[0], 1u);
            if (old == phase * 128u + 127u) {
                atomicExch(&d_gsync[1], phase + 1u);
            } else {
                while (*((volatile unsigned*)&d_gsync[1]) <= phase) {}
            }
            __threadfence();
        }
        __syncthreads();
        phase++;
    }
}

// ---------------------------------------------------------------------------
// fp32 -> fp16 hi/lo split ([N,K] weights)
// ---------------------------------------------------------------------------
__global__ void split_k(const float* __restrict__ A,
                        __half* __restrict__ hi, __half* __restrict__ lo, long n)
{
    const long i = ((long)blockIdx.x * blockDim.x + threadIdx.x) * 4;
    if (i >= n) return;
    const float4 v = *reinterpret_cast<const float4*>(A + i);
    float a[4] = {v.x, v.y, v.z, v.w};
    __half h[4], l[4];
#pragma unroll
    for (int k = 0; k < 4; k++) {
        h[k] = __float2half(a[k]);
        l[k] = __float2half(a[k] - __half2float(h[k]));
    }
    *reinterpret_cast<uint2*>(hi + i) = *reinterpret_cast<uint2*>(h);
    *reinterpret_cast<uint2*>(lo + i) = *reinterpret_cast<uint2*>(l);
}

// transposing fp32 [K,N] -> fp16 hi/lo [N,K]
__global__ void splitT_k(const float* __restrict__ in,
                         __half* __restrict__ hi, __half* __restrict__ lo,
                         int K, int N)
{
    __shared__ float tile[32][33];
    int x = blockIdx.x * 32 + threadIdx.x;
    int y = blockIdx.y * 32 + threadIdx.y;
    if (x < N && y < K) tile[threadIdx.y][threadIdx.x] = in[(size_t)y * N + x];
    __syncthreads();
    const int n = blockIdx.x * 32 + threadIdx.y;
    const int k = blockIdx.y * 32 + threadIdx.x;
    if (n < N && k < K) {
        const float w = tile[threadIdx.x][threadIdx.y];
        const __half h = __float2half(w);
        hi[(size_t)n * K + k] = h;
        lo[(size_t)n * K + k] = __float2half(w - __half2float(h));
    }
}

// ---------------------------------------------------------------------------
// Adjacency contraction, RB=50. blend given as fp16 hi/lo pair (lstm h).
// ---------------------------------------------------------------------------
__launch_bounds__(256)
__global__ void adj_gemm(const float* __restrict__ adj, const float* __restrict__ T,
                         float* __restrict__ C, int relu,
                         const __half* __restrict__ bhi, const __half* __restrict__ blo,
                         __half* __restrict__ ohi, __half* __restrict__ olo)
{
    constexpr int RB = 50;
    constexpr int N = BATCH * HID;
    __shared__ float as[RB][LSEQ];
    const int r0 = blockIdx.y * RB;
    const int n  = blockIdx.x * 256 + threadIdx.x;

    for (int i = threadIdx.x; i < RB * LSEQ; i += 256)
        as[i / LSEQ][i % LSEQ] = adj[(size_t)(r0 + i / LSEQ) * LSEQ + (i % LSEQ)];
    __syncthreads();

    float acc[RB];
#pragma unroll
    for (int r = 0; r < RB; r++) acc[r] = 0.0f;
    for (int k = 0; k < LSEQ; k++) {
        const float t = T[(size_t)k * N + n];
#pragma unroll
        for (int r = 0; r < RB; r++) acc[r] = fmaf(as[r][k], t, acc[r]);
    }
#pragma unroll
    for (int r = 0; r < RB; r++) {
        float v = acc[r];
        if (relu) v = fmaxf(v, 0.0f);
        const size_t idx = (size_t)(r0 + r) * N + n;
        if (bhi) {
            const float bl = __half2float(bhi[idx]) + __half2float(blo[idx]);
            const float m = (1.0f - SIGMA_MIX) * v + SIGMA_MIX * bl;
            const __half h = __float2half(m);
            ohi[idx] = h;
            olo[idx] = __float2half(m - __half2float(h));
        } else {
            C[idx] = v;
        }
    }
}

// ---------------------------------------------------------------------------
// Embedding: emits qemb fp32 AND qa directly as fp16 hi/lo
// ---------------------------------------------------------------------------
__global__ void embed_k(const int* __restrict__ q, const int* __restrict__ c,
                        const int* __restrict__ r, const int* __restrict__ qsh,
                        const int* __restrict__ csh, const int* __restrict__ rsh,
                        const float* __restrict__ Wq, const float* __restrict__ Wc,
                        const float* __restrict__ Wr,
                        __half* __restrict__ qah, __half* __restrict__ qal,
                        float* __restrict__ qemb)
{
    const long idx = (long)blockIdx.x * blockDim.x + threadIdx.x;
    if (idx >= (long)LSEQ * BATCH * HID) return;
    const int e = (int)(idx % HID);
    const int b = (int)((idx / HID) % BATCH);
    const int t = (int)(idx / ((long)HID * BATCH));
    const int pid = (t == 0) ? q[b * SEQ]  : qsh[b * SEQ + t - 1];
    const int cid = (t == 0) ? c[b * SEQ]  : csh[b * SEQ + t - 1];
    const int tgt = (t == 0) ? r[b * SEQ]  : rsh[b * SEQ + t - 1];
    const float qe = Wq[(size_t)pid * EMB + e] + Wc[(size_t)cid * EMB + e];
    qemb[idx] = qe;
    const float qav = qe + Wr[(size_t)tgt * EMB + e];
    const __half h = __float2half(qav);
    qah[idx] = h;
    qal[idx] = __float2half(qav - __half2float(h));
}

__global__ void bsum_k(const float* __restrict__ bih, const float* __restrict__ bhh,
                       float* __restrict__ bsum)
{
    const int i = blockIdx.x * blockDim.x + threadIdx.x;
    if (i < NLAY * G4H) bsum[i] = bih[i] + bhh[i];
}

__global__ void concat_half_k(const float* __restrict__ hg, const float* __restrict__ qe,
                              __half* __restrict__ hi, __half* __restrict__ lo)
{
    const long idx = (long)blockIdx.x * blockDim.x + threadIdx.x;
    if (idx >= (long)BATCH * SEQ * (2 * EMB)) return;
    const int f = (int)(idx % (2 * EMB));
    const int s = (int)((idx / (2 * EMB)) % SEQ);
    const int b = (int)(idx / ((long)(2 * EMB) * SEQ));
    const size_t src = ((size_t)(s + 1) * BATCH + b) * HID;
    const float v = (f < EMB) ? hg[src + f] : qe[src + (f - EMB)];
    const __half h = __float2half(v);
    hi[idx] = h;
    lo[idx] = __float2half(v - __half2float(h));
}

__global__ void mlp3_k(const float* __restrict__ X, const float* __restrict__ W3,
                       const float* __restrict__ b3, float* __restrict__ y, int M)
{
    const int warp = (blockIdx.x * blockDim.x + threadIdx.x) >> 5;
    const int lane = threadIdx.x & 31;
    if (warp >= M) return;
    const float* xr = X + (size_t)warp * NFC2;
    float s = 0.0f;
#pragma unroll
    for (int k = lane; k < NFC2; k += 32) s = fmaf(xr[k], W3[k], s);
#pragma unroll
    for (int o = 16; o > 0; o >>= 1) s += __shfl_down_sync(0xffffffffu, s, o);
    if (lane == 0) y[warp] = 1.0f / (1.0f + expf(-(s + b3[0])));
}

// ---------------------------------------------------------------------------
// Orchestration
// ---------------------------------------------------------------------------
extern "C" void kernel_launch(void* const* d_in, const int* in_sizes, int n_in,
                              void* d_out, int out_size)
{
    const int   *q   = (const int*)d_in[0],  *c   = (const int*)d_in[1];
    const int   *r   = (const int*)d_in[2],  *qsh = (const int*)d_in[3];
    const int   *csh = (const int*)d_in[4],  *rsh = (const int*)d_in[5];
    const float *adj = (const float*)d_in[6];
    const float *Wq  = (const float*)d_in[7], *Wc  = (const float*)d_in[8];
    const float *Wr  = (const float*)d_in[9];
    const float *Wih = (const float*)d_in[10], *Whh = (const float*)d_in[11];
    const float *bih = (const float*)d_in[12], *bhh = (const float*)d_in[13];
    const float *Wg  = (const float*)d_in[14];
    const float *W1  = (const float*)d_in[15], *b1 = (const float*)d_in[16];
    const float *W2  = (const float*)d_in[17], *b2 = (const float*)d_in[18];
    const float *W3  = (const float*)d_in[19], *b3 = (const float*)d_in[20];
    float* y = (float*)d_out;

    float *qemb, *gx, *t0, *g0, *m2, *bsum;
    unsigned* gsync;
    __half *ah, *al, *bh, *bl, *hsh, *hsl;
    cudaGetSymbolAddress((void**)&qemb, d_qemb);
    cudaGetSymbolAddress((void**)&gx,   d_gx);
    cudaGetSymbolAddress((void**)&t0,   d_t0);
    cudaGetSymbolAddress((void**)&g0,   d_g0);
    cudaGetSymbolAddress((void**)&m2,   d_m2);
    cudaGetSymbolAddress((void**)&bsum, d_bsum);
    cudaGetSymbolAddress((void**)&gsync, d_gsync);
    cudaGetSymbolAddress((void**)&ah,   d_ah);
    cudaGetSymbolAddress((void**)&al,   d_al);
    cudaGetSymbolAddress((void**)&bh,   d_bh);
    cudaGetSymbolAddress((void**)&bl,   d_bl);
    cudaGetSymbolAddress((void**)&hsh,  d_hsh);
    cudaGetSymbolAddress((void**)&hsl,  d_hsl);

    cudaFuncSetAttribute(mma_gemm, cudaFuncAttributeMaxDynamicSharedMemorySize, MMA_SMEM);
    cudaFuncSetAttribute(lstm_layer_mma, cudaFuncAttributeMaxDynamicSharedMemorySize, LSTM2_SMEM);

    const long NE = (long)LSEQ * BATCH * HID;

    // ---- prep ----
    bsum_k<<<(NLAY * G4H + 255) / 256, 256>>>(bih, bhh, bsum);
    embed_k<<<(unsigned)((NE + 255) / 256), 256>>>(q, c, r, qsh, csh, rsh,
                                                   Wq, Wc, Wr, hsh, hsl, qemb);
    cudaMemsetAsync(gsync, 0, 8, 0);

    // ---- 5-layer LSTM ----
    for (int l = 0; l < NLAY; l++) {
        split_k<<<(unsigned)((long)G4H * HID / 4 / 256), 256>>>(
            Wih + (size_t)l * G4H * HID, bh, bl, (long)G4H * HID);
        mma_gemm<<<dim3(G4H / 128, (LSEQ * BATCH) / 128), 256, MMA_SMEM>>>(
            hsh, hsl, bh, bl, gx, nullptr, nullptr, G4H, HID,
            bsum + (size_t)l * G4H, 0);
        lstm_layer_mma<<<128, 256, LSTM2_SMEM>>>(
            gx, Whh + (size_t)l * G4H * HID, hsh, hsl, (unsigned)(l * LSEQ));
    }

    // ---- 5 GCN layers (blend = hsh/hsl of last LSTM layer) ----
    splitT_k<<<dim3(16, 16), dim3(32, 32)>>>(Wg, bh, bl, HID, HID);
    mma_gemm<<<dim3(HID / 128, (LSEQ * BATCH) / 128), 256, MMA_SMEM>>>(
        hsh, hsl, bh, bl, t0, nullptr, nullptr, HID, HID, nullptr, 0);
    adj_gemm<<<dim3((BATCH * HID) / 256, LSEQ / 50), 256>>>(
        adj, t0, nullptr, 1, hsh, hsl, ah, al);
    for (int i = 1; i < 5; i++) {
        splitT_k<<<dim3(16, 16), dim3(32, 32)>>>(Wg + (size_t)i * HID * HID, bh, bl,
                                                 HID, HID);
        mma_gemm<<<dim3(HID / 128, (LSEQ * BATCH) / 128), 256, MMA_SMEM>>>(
            ah, al, bh, bl, t0, nullptr, nullptr, HID, HID, nullptr, 0);
        if (i < 4) {
            adj_gemm<<<dim3((BATCH * HID) / 256, LSEQ / 50), 256>>>(
                adj, t0, nullptr, 1, hsh, hsl, ah, al);
        } else {
            adj_gemm<<<dim3((BATCH * HID) / 256, LSEQ / 50), 256>>>(
                adj, t0, g0, 0, nullptr, nullptr, nullptr, nullptr);
        }
    }

    // ---- concat + MLP head ----
    {
        const long n = (long)BATCH * SEQ * (2 * EMB);
        concat_half_k<<<(unsigned)((n + 255) / 256), 256>>>(g0, qemb, ah, al);
    }
    const int M = BATCH * SEQ;   // 50944 = 398*128
    splitT_k<<<dim3(16, 32), dim3(32, 32)>>>(W1, bh, bl, 2 * EMB, NFC1);
    mma_gemm<<<dim3(NFC1 / 128, M / 128), 256, MMA_SMEM>>>(
        ah, al, bh, bl, nullptr, hsh, hsl, NFC1, 2 * EMB, b1, 1);
    splitT_k<<<dim3(8, 16), dim3(32, 32)>>>(W2, bh, bl, NFC1, NFC2);
    mma_gemm<<<dim3(NFC2 / 128, M / 128), 256, MMA_SMEM>>>(
        hsh, hsl, bh, bl, m2, nullptr, nullptr, NFC2, NFC1, b2, 1);
    mlp3_k<<<(M * 32 + 255) / 256, 256>>>(m2, W3, b3, y, M);
}

// round 17
// speedup vs baseline: 1.1750x; 1.0403x over previous
#include <cuda_runtime.h>
#include <cuda_fp16.h>
#include <math.h>
#include <stdint.h>

#define BATCH 256
#define SEQ 199
#define LSEQ 200
#define EMB 512
#define HID 512
#define G4H 2048
#define NLAY 5
#define NFC1 512
#define NFC2 256
#define SIGMA_MIX 0.5f

#define SMEM_SWIZZLE_128B(b) ((b) ^ (((b) >> 3) & 0x70))

__device__ __forceinline__ uint32_t smem_to_u32(const void* p) {
    uint32_t a;
    asm("{ .reg .u64 t; cvta.to.shared.u64 t, %1; cvt.u32.u64 %0, t; }" : "=r"(a) : "l"(p));
    return a;
}
__device__ __forceinline__ void cp_async16(uint32_t saddr, const void* gaddr) {
    asm volatile("cp.async.cg.shared.global [%0], [%1], 16;" :: "r"(saddr), "l"(gaddr));
}
#define CP_COMMIT() asm volatile("cp.async.commit_group;" ::: "memory")
#define CP_WAIT(N)  asm volatile("cp.async.wait_group %0;" :: "n"(N) : "memory")

__device__ __forceinline__ void ldmatrix_x4(uint32_t* r, uint32_t addr) {
    asm volatile("ldmatrix.sync.aligned.m8n8.x4.shared.b16 {%0,%1,%2,%3}, [%4];"
                 : "=r"(r[0]), "=r"(r[1]), "=r"(r[2]), "=r"(r[3]) : "r"(addr));
}
__device__ __forceinline__ void mma_f16(float* d, const uint32_t* a, uint32_t b0, uint32_t b1) {
    asm volatile("mma.sync.aligned.m16n8k16.row.col.f32.f16.f16.f32 "
                 "{%0,%1,%2,%3}, {%4,%5,%6,%7}, {%8,%9}, {%0,%1,%2,%3};"
                 : "+f"(d[0]), "+f"(d[1]), "+f"(d[2]), "+f"(d[3])
                 : "r"(a[0]), "r"(a[1]), "r"(a[2]), "r"(a[3]), "r"(b0), "r"(b1));
}

// recurrence B smem addressing: row n = 1024B; XOR in-segment 16B chunk bits with n&7
__device__ __forceinline__ uint32_t baddr(int n, int kb) {
    return (uint32_t)(n * 1024 + (kb ^ ((n & 7) << 4)));
}

// hardware tanh approximation (sm_75+): 1 MUFU op
__device__ __forceinline__ float tanh_ap(float x) {
    float y;
    asm("tanh.approx.f32 %0, %1;" : "=f"(y) : "f"(x));
    return y;
}
__device__ __forceinline__ float sig_ap(float x) {
    return fmaf(0.5f, tanh_ap(0.5f * x), 0.5f);
}

// ---------------------------------------------------------------------------
// Static device scratch
// ---------------------------------------------------------------------------
__device__ float d_qemb[(size_t)LSEQ*BATCH*HID];
__device__ float d_gx  [(size_t)LSEQ*BATCH*G4H];
__device__ float d_t0  [(size_t)LSEQ*BATCH*HID];
__device__ float d_g0  [(size_t)LSEQ*BATCH*HID];
__device__ float d_m2  [(size_t)BATCH*SEQ*NFC2];
__device__ float d_bsum[(size_t)NLAY*G4H];
__device__ unsigned d_gsync[2];
__device__ __half d_ah  [(size_t)LSEQ*BATCH*1024];
__device__ __half d_al  [(size_t)LSEQ*BATCH*1024];
__device__ __half d_bh  [(size_t)G4H*HID];
__device__ __half d_bl  [(size_t)G4H*HID];
__device__ __half d_hsh [(size_t)LSEQ*BATCH*HID];
__device__ __half d_hsl [(size_t)LSEQ*BATCH*HID];

__device__ __forceinline__ float sigf(float x) { return 1.0f / (1.0f + expf(-x)); }

// ---------------------------------------------------------------------------
// fp16 fused-3-group NT GEMM, 2-blocks-per-SM (unchanged — passing).
// ---------------------------------------------------------------------------
#define MMA_SMEM 98304

__global__ __launch_bounds__(256, 2)
void mma_gemm(const __half* __restrict__ Ahi, const __half* __restrict__ Alo,
              const __half* __restrict__ Bhi, const __half* __restrict__ Blo,
              float* __restrict__ C, __half* __restrict__ Chi, __half* __restrict__ Clo,
              int N, int K, const float* __restrict__ bias, int relu)
{
    extern __shared__ char smem[];
    const uint32_t smem_u = smem_to_u32(smem);
    const int tid = threadIdx.x;
    const int wid = tid >> 5, lane = tid & 31;
    const int warp_m = wid & 3, warp_n = wid >> 2;
    const long bm = (long)blockIdx.y * 128;
    const long bn = (long)blockIdx.x * 128;
    const int TI = K >> 5;

    float acc[2][8][4];
#pragma unroll
    for (int i = 0; i < 2; i++)
#pragma unroll
        for (int j = 0; j < 8; j++)
#pragma unroll
            for (int k = 0; k < 4; k++) acc[i][j][k] = 0.0f;

    auto issue_load = [&](int stage, int kt) {
        const long k0 = (long)kt << 5;
        const uint32_t s0 = smem_u + stage * 32768;
#pragma unroll
        for (int c = 0; c < 8; c++) {
            const int cid = tid + c * 256;
            const int mat = cid >> 10;
            const int rem = cid & 1023;
            const int row = rem >> 3;
            const int o   = rem & 7;
            const int opnd = o >> 2;
            const int kch  = o & 3;
            const uint32_t sw = SMEM_SWIZZLE_128B((uint32_t)(row * 128 + o * 16));
            const __half* src = mat ? (opnd ? Blo : Bhi) : (opnd ? Alo : Ahi);
            const long base = mat ? bn : bm;
            cp_async16(s0 + mat * 16384 + sw,
                       src + (base + row) * (long)K + k0 + kch * 8);
        }
    };

    issue_load(0, 0); CP_COMMIT();
    issue_load(1, 1); CP_COMMIT();

    for (int j = 0; j < TI; j++) {
        if (j + 2 < TI)      { issue_load((j + 2) % 3, j + 2); CP_COMMIT(); CP_WAIT(2); }
        else if (j + 1 < TI) { CP_WAIT(1); }
        else                 { CP_WAIT(0); }
        __syncthreads();

        const uint32_t s0 = smem_u + (j % 3) * 32768;
#pragma unroll
        for (int ks = 0; ks < 2; ks++) {
            uint32_t afh[2][4], afl[2][4];
#pragma unroll
            for (int mt = 0; mt < 2; mt++) {
                const int row = warp_m * 32 + mt * 16 + (lane & 15);
                const int colb = ks * 32 + (lane >> 4) * 16;
                ldmatrix_x4(afh[mt], s0 + SMEM_SWIZZLE_128B((uint32_t)(row * 128 + colb)));
                ldmatrix_x4(afl[mt], s0 + SMEM_SWIZZLE_128B((uint32_t)(row * 128 + 64 + colb)));
            }
            uint32_t bfh[4][4], bfl[4][4];
#pragma unroll
            for (int nt2 = 0; nt2 < 4; nt2++) {
                const int nrow = warp_n * 64 + nt2 * 16 + ((lane >> 4) << 3) + (lane & 7);
                const int colb = ks * 32 + ((lane >> 3) & 1) * 16;
                ldmatrix_x4(bfh[nt2], s0 + 16384 + SMEM_SWIZZLE_128B((uint32_t)(nrow * 128 + colb)));
                ldmatrix_x4(bfl[nt2], s0 + 16384 + SMEM_SWIZZLE_128B((uint32_t)(nrow * 128 + 64 + colb)));
            }
#pragma unroll
            for (int mt = 0; mt < 2; mt++)
#pragma unroll
                for (int nt = 0; nt < 8; nt++) {
                    const uint32_t b0 = bfh[nt >> 1][(nt & 1) * 2 + 0];
                    const uint32_t b1 = bfh[nt >> 1][(nt & 1) * 2 + 1];
                    mma_f16(acc[mt][nt], afh[mt], b0, b1);
                    mma_f16(acc[mt][nt], afl[mt], b0, b1);
                    mma_f16(acc[mt][nt], afh[mt],
                            bfl[nt >> 1][(nt & 1) * 2 + 0],
                            bfl[nt >> 1][(nt & 1) * 2 + 1]);
                }
        }
        __syncthreads();
    }

#pragma unroll
    for (int mt = 0; mt < 2; mt++) {
        const long m0 = bm + warp_m * 32 + mt * 16 + (lane >> 2);
#pragma unroll
        for (int nt = 0; nt < 8; nt++) {
            const long nn = bn + warp_n * 64 + nt * 8 + (lane & 3) * 2;
            float bx = 0.0f, by = 0.0f;
            if (bias) { const float2 bv = *reinterpret_cast<const float2*>(&bias[nn]); bx = bv.x; by = bv.y; }
            float v0 = acc[mt][nt][0] + bx, v1 = acc[mt][nt][1] + by;
            float v2 = acc[mt][nt][2] + bx, v3 = acc[mt][nt][3] + by;
            if (relu) {
                v0 = fmaxf(v0, 0.0f); v1 = fmaxf(v1, 0.0f);
                v2 = fmaxf(v2, 0.0f); v3 = fmaxf(v3, 0.0f);
            }
            if (C) {
                *reinterpret_cast<float2*>(&C[m0 * (long)N + nn])       = make_float2(v0, v1);
                *reinterpret_cast<float2*>(&C[(m0 + 8) * (long)N + nn]) = make_float2(v2, v3);
            }
            if (Chi) {
                __half h0 = __float2half(v0), h1 = __float2half(v1);
                __half h2 = __float2half(v2), h3 = __float2half(v3);
                __half l0 = __float2half(v0 - __half2float(h0));
                __half l1 = __float2half(v1 - __half2float(h1));
                __half l2 = __float2half(v2 - __half2float(h2));
                __half l3 = __float2half(v3 - __half2float(h3));
                *reinterpret_cast<__half2*>(&Chi[m0 * (long)N + nn])       = __halves2half2(h0, h1);
                *reinterpret_cast<__half2*>(&Chi[(m0 + 8) * (long)N + nn]) = __halves2half2(h2, h3);
                *reinterpret_cast<__half2*>(&Clo[m0 * (long)N + nn])       = __halves2half2(l0, l1);
                *reinterpret_cast<__half2*>(&Clo[(m0 + 8) * (long)N + nn]) = __halves2half2(l2, l3);
            }
        }
    }
}

// ---------------------------------------------------------------------------
// Persistent tensor-core LSTM layer (unchanged — passing)
// ---------------------------------------------------------------------------
#define LSTM2_SMEM 229376

__global__ __launch_bounds__(256)
void lstm_layer_mma(const float* __restrict__ gx, const float* __restrict__ Whh,
                    __half* __restrict__ hsh, __half* __restrict__ hsl,
                    unsigned phase0)
{
    extern __shared__ char smem[];
    const uint32_t smem_u = smem_to_u32(smem);
    const uint32_t Ast_u = smem_u + 131072;

    const int tid = threadIdx.x;
    const int wid = tid >> 5, lane = tid & 31;
    const int warp_m = wid & 3;
    const int warp_n = wid >> 2;
    const int bm = (blockIdx.x & 3) * 64;
    const int c0 = (blockIdx.x >> 2) * 16;

    for (int i = tid; i < 64 * 512; i += 256) {
        const int n = i >> 9, k = i & 511;
        const int chunk = n >> 4, w16 = n & 15;
        const int gpair = w16 >> 3, rest = w16 & 7;
        const int hl = chunk * 4 + (rest >> 1);
        const int g  = gpair * 2 + (rest & 1);
        const float w = Whh[(size_t)(g * 512 + c0 + hl) * 512 + k];
        const __half h = __float2half(w);
        const __half l = __float2half(w - __half2float(h));
        const uint32_t off = baddr(n, k * 2);
        *reinterpret_cast<__half*>(smem + off) = h;
        *reinterpret_cast<__half*>(smem + 65536 + off) = l;
    }
    __syncthreads();

    float creg[4];
#pragma unroll
    for (int i = 0; i < 4; i++) creg[i] = 0.0f;
    unsigned phase = phase0;

    for (int t = 0; t < LSEQ; t++) {
        float acc[4][4];
#pragma unroll
        for (int i = 0; i < 4; i++)
#pragma unroll
            for (int j = 0; j < 4; j++) acc[i][j] = 0.0f;

        if (t > 0) {
            const __half* hhi = hsh + (size_t)(t - 1) * BATCH * HID;
            const __half* hlo = hsl + (size_t)(t - 1) * BATCH * HID;

            auto issueA = [&](int stage, int kc) {
                const uint32_t sa = Ast_u + stage * 32768;
#pragma unroll
                for (int c = 0; c < 8; c++) {
                    const int cid = tid + c * 256;
                    const int sub = cid >> 10;
                    const int plane = (cid >> 9) & 1;
                    const int rr = cid & 511;
                    const int row = rr >> 3, o16 = rr & 7;
                    const uint32_t sw = SMEM_SWIZZLE_128B((uint32_t)(row * 128 + o16 * 16));
                    const __half* src = plane ? hlo : hhi;
                    cp_async16(sa + sub * 16384 + plane * 8192 + sw,
                               src + (bm + row) * 512 + kc * 128 + sub * 64 + o16 * 8);
                }
            };
            issueA(0, 0); CP_COMMIT();
            issueA(1, 1); CP_COMMIT();
            for (int kc = 0; kc < 4; kc++) {
                if (kc + 2 < 4)      { issueA((kc + 2) % 3, kc + 2); CP_COMMIT(); CP_WAIT(2); }
                else if (kc + 1 < 4) { CP_WAIT(1); }
                else                 { CP_WAIT(0); }
                __syncthreads();
                const uint32_t sa = Ast_u + (kc % 3) * 32768;
#pragma unroll
                for (int ks = 0; ks < 8; ks++) {
                    const int sub = ks >> 2, ksl = ks & 3;
                    uint32_t ahf[4], alf[4];
                    {
                        const int row = warp_m * 16 + (lane & 15);
                        const int col = ksl * 32 + (lane >> 4) * 16;
                        const uint32_t ad = sa + sub * 16384
                                          + SMEM_SWIZZLE_128B((uint32_t)(row * 128 + col));
                        ldmatrix_x4(ahf, ad);
                        ldmatrix_x4(alf, ad + 8192);
                    }
                    uint32_t bhf[2][4], blf[2][4];
#pragma unroll
                    for (int g2 = 0; g2 < 2; g2++) {
                        const int n_r = warp_n * 32 + g2 * 16 + ((lane >> 4) << 3) + (lane & 7);
                        const int khalf = kc * 128 + ks * 16 + ((lane >> 3) & 1) * 8;
                        const uint32_t off = baddr(n_r, khalf * 2);
                        ldmatrix_x4(bhf[g2], smem_u + off);
                        ldmatrix_x4(blf[g2], smem_u + 65536 + off);
                    }
#pragma unroll
                    for (int nt = 0; nt < 4; nt++) {
                        const uint32_t b0 = bhf[nt >> 1][(nt & 1) * 2 + 0];
                        const uint32_t b1 = bhf[nt >> 1][(nt & 1) * 2 + 1];
                        mma_f16(acc[nt], ahf, b0, b1);
                        mma_f16(acc[nt], alf, b0, b1);
                        mma_f16(acc[nt], ahf,
                                blf[nt >> 1][(nt & 1) * 2 + 0],
                                blf[nt >> 1][(nt & 1) * 2 + 1]);
                    }
                }
                __syncthreads();
            }
        }

        {
            __half* whi = hsh + (size_t)t * BATCH * HID;
            __half* wlo = hsl + (size_t)t * BATCH * HID;
            const float* gxp = gx + (size_t)t * BATCH * G4H;
#pragma unroll
            for (int c = 0; c < 2; c++) {
                const int hl = (warp_n * 2 + c) * 4 + (lane & 3);
#pragma unroll
                for (int rh = 0; rh < 2; rh++) {
                    const int b = bm + warp_m * 16 + (lane >> 2) + rh * 8;
                    const size_t gb = (size_t)b * G4H + c0 + hl;
                    const float gi = gxp[gb]        + acc[c * 2 + 0][rh * 2 + 0];
                    const float gf = gxp[gb + 512]  + acc[c * 2 + 0][rh * 2 + 1];
                    const float gg = gxp[gb + 1024] + acc[c * 2 + 1][rh * 2 + 0];
                    const float go = gxp[gb + 1536] + acc[c * 2 + 1][rh * 2 + 1];
                    const int ci = c * 2 + rh;
                    const float cv = sig_ap(gf) * creg[ci] + sig_ap(gi) * tanh_ap(gg);
                    const float hv = sig_ap(go) * tanh_ap(cv);
                    creg[ci] = cv;
                    const size_t oidx = (size_t)b * HID + c0 + hl;
                    const __half hh = __float2half(hv);
                    whi[oidx] = hh;
                    wlo[oidx] = __float2half(hv - __half2float(hh));
                }
            }
        }

        __syncthreads();
        if (tid == 0) {
            __threadfence();
            const unsigned old = atomicAdd(&d_gsync[0], 1u);
            if (old == phase * 128u + 127u) {
                atomicExch(&d_gsync[1], phase + 1u);
            } else {
                while (*((volatile unsigned*)&d_gsync[1]) <= phase) {}
            }
            __threadfence();
        }
        __syncthreads();
        phase++;
    }
}

// ---------------------------------------------------------------------------
// fp32 -> fp16 hi/lo split ([N,K] weights)
// ---------------------------------------------------------------------------
__global__ void split_k(const float* __restrict__ A,
                        __half* __restrict__ hi, __half* __restrict__ lo, long n)
{
    const long i = ((long)blockIdx.x * blockDim.x + threadIdx.x) * 4;
    if (i >= n) return;
    const float4 v = *reinterpret_cast<const float4*>(A + i);
    float a[4] = {v.x, v.y, v.z, v.w};
    __half h[4], l[4];
#pragma unroll
    for (int k = 0; k < 4; k++) {
        h[k] = __float2half(a[k]);
        l[k] = __float2half(a[k] - __half2float(h[k]));
    }
    *reinterpret_cast<uint2*>(hi + i) = *reinterpret_cast<uint2*>(h);
    *reinterpret_cast<uint2*>(lo + i) = *reinterpret_cast<uint2*>(l);
}

// transposing fp32 [K,N] -> fp16 hi/lo [N,K]
__global__ void splitT_k(const float* __restrict__ in,
                         __half* __restrict__ hi, __half* __restrict__ lo,
                         int K, int N)
{
    __shared__ float tile[32][33];
    int x = blockIdx.x * 32 + threadIdx.x;
    int y = blockIdx.y * 32 + threadIdx.y;
    if (x < N && y < K) tile[threadIdx.y][threadIdx.x] = in[(size_t)y * N + x];
    __syncthreads();
    const int n = blockIdx.x * 32 + threadIdx.y;
    const int k = blockIdx.y * 32 + threadIdx.x;
    if (n < N && k < K) {
        const float w = tile[threadIdx.x][threadIdx.y];
        const __half h = __float2half(w);
        hi[(size_t)n * K + k] = h;
        lo[(size_t)n * K + k] = __float2half(w - __half2float(h));
    }
}

// ---------------------------------------------------------------------------
// Adjacency contraction, register-blocked: RB=25 rows x TN=4 columns/thread.
// Each as[r][k] LDS (warp-broadcast) feeds 4 FMAs -> FMA-bound, not LDS-bound.
// Columns strided by 256 so each of the 4 LDG streams is fully coalesced.
// ---------------------------------------------------------------------------
__launch_bounds__(256)
__global__ void adj_gemm(const float* __restrict__ adj, const float* __restrict__ T,
                         float* __restrict__ C, int relu,
                         const __half* __restrict__ bhi, const __half* __restrict__ blo,
                         __half* __restrict__ ohi, __half* __restrict__ olo)
{
    constexpr int RB = 25;
    constexpr int TN = 4;
    constexpr int N = BATCH * HID;
    __shared__ float as[RB][LSEQ];
    const int r0 = blockIdx.y * RB;
    const int n0 = blockIdx.x * (256 * TN) + threadIdx.x;

    for (int i = threadIdx.x; i < RB * LSEQ; i += 256)
        as[i / LSEQ][i % LSEQ] = adj[(size_t)(r0 + i / LSEQ) * LSEQ + (i % LSEQ)];
    __syncthreads();

    float acc[RB][TN];
#pragma unroll
    for (int r = 0; r < RB; r++)
#pragma unroll
        for (int j = 0; j < TN; j++) acc[r][j] = 0.0f;

    for (int k = 0; k < LSEQ; k++) {
        float t[TN];
        const float* Tk = T + (size_t)k * N + n0;
#pragma unroll
        for (int j = 0; j < TN; j++) t[j] = Tk[j * 256];
#pragma unroll
        for (int r = 0; r < RB; r++) {
            const float a = as[r][k];
#pragma unroll
            for (int j = 0; j < TN; j++) acc[r][j] = fmaf(a, t[j], acc[r][j]);
        }
    }
#pragma unroll
    for (int r = 0; r < RB; r++) {
#pragma unroll
        for (int j = 0; j < TN; j++) {
            float v = acc[r][j];
            if (relu) v = fmaxf(v, 0.0f);
            const size_t idx = (size_t)(r0 + r) * N + n0 + j * 256;
            if (bhi) {
                const float bl = __half2float(bhi[idx]) + __half2float(blo[idx]);
                const float m = (1.0f - SIGMA_MIX) * v + SIGMA_MIX * bl;
                const __half h = __float2half(m);
                ohi[idx] = h;
                olo[idx] = __float2half(m - __half2float(h));
            } else {
                C[idx] = v;
            }
        }
    }
}

// ---------------------------------------------------------------------------
// Embedding: emits qemb fp32 AND qa directly as fp16 hi/lo
// ---------------------------------------------------------------------------
__global__ void embed_k(const int* __restrict__ q, const int* __restrict__ c,
                        const int* __restrict__ r, const int* __restrict__ qsh,
                        const int* __restrict__ csh, const int* __restrict__ rsh,
                        const float* __restrict__ Wq, const float* __restrict__ Wc,
                        const float* __restrict__ Wr,
                        __half* __restrict__ qah, __half* __restrict__ qal,
                        float* __restrict__ qemb)
{
    const long idx = (long)blockIdx.x * blockDim.x + threadIdx.x;
    if (idx >= (long)LSEQ * BATCH * HID) return;
    const int e = (int)(idx % HID);
    const int b = (int)((idx / HID) % BATCH);
    const int t = (int)(idx / ((long)HID * BATCH));
    const int pid = (t == 0) ? q[b * SEQ]  : qsh[b * SEQ + t - 1];
    const int cid = (t == 0) ? c[b * SEQ]  : csh[b * SEQ + t - 1];
    const int tgt = (t == 0) ? r[b * SEQ]  : rsh[b * SEQ + t - 1];
    const float qe = Wq[(size_t)pid * EMB + e] + Wc[(size_t)cid * EMB + e];
    qemb[idx] = qe;
    const float qav = qe + Wr[(size_t)tgt * EMB + e];
    const __half h = __float2half(qav);
    qah[idx] = h;
    qal[idx] = __float2half(qav - __half2float(h));
}

__global__ void bsum_k(const float* __restrict__ bih, const float* __restrict__ bhh,
                       float* __restrict__ bsum)
{
    const int i = blockIdx.x * blockDim.x + threadIdx.x;
    if (i < NLAY * G4H) bsum[i] = bih[i] + bhh[i];
}

__global__ void concat_half_k(const float* __restrict__ hg, const float* __restrict__ qe,
                              __half* __restrict__ hi, __half* __restrict__ lo)
{
    const long idx = (long)blockIdx.x * blockDim.x + threadIdx.x;
    if (idx >= (long)BATCH * SEQ * (2 * EMB)) return;
    const int f = (int)(idx % (2 * EMB));
    const int s = (int)((idx / (2 * EMB)) % SEQ);
    const int b = (int)(idx / ((long)(2 * EMB) * SEQ));
    const size_t src = ((size_t)(s + 1) * BATCH + b) * HID;
    const float v = (f < EMB) ? hg[src + f] : qe[src + (f - EMB)];
    const __half h = __float2half(v);
    hi[idx] = h;
    lo[idx] = __float2half(v - __half2float(h));
}

__global__ void mlp3_k(const float* __restrict__ X, const float* __restrict__ W3,
                       const float* __restrict__ b3, float* __restrict__ y, int M)
{
    const int warp = (blockIdx.x * blockDim.x + threadIdx.x) >> 5;
    const int lane = threadIdx.x & 31;
    if (warp >= M) return;
    const float* xr = X + (size_t)warp * NFC2;
    float s = 0.0f;
#pragma unroll
    for (int k = lane; k < NFC2; k += 32) s = fmaf(xr[k], W3[k], s);
#pragma unroll
    for (int o = 16; o > 0; o >>= 1) s += __shfl_down_sync(0xffffffffu, s, o);
    if (lane == 0) y[warp] = 1.0f / (1.0f + expf(-(s + b3[0])));
}

// ---------------------------------------------------------------------------
// Orchestration
// ---------------------------------------------------------------------------
extern "C" void kernel_launch(void* const* d_in, const int* in_sizes, int n_in,
                              void* d_out, int out_size)
{
    const int   *q   = (const int*)d_in[0],  *c   = (const int*)d_in[1];
    const int   *r   = (const int*)d_in[2],  *qsh = (const int*)d_in[3];
    const int   *csh = (const int*)d_in[4],  *rsh = (const int*)d_in[5];
    const float *adj = (const float*)d_in[6];
    const float *Wq  = (const float*)d_in[7], *Wc  = (const float*)d_in[8];
    const float *Wr  = (const float*)d_in[9];
    const float *Wih = (const float*)d_in[10], *Whh = (const float*)d_in[11];
    const float *bih = (const float*)d_in[12], *bhh = (const float*)d_in[13];
    const float *Wg  = (const float*)d_in[14];
    const float *W1  = (const float*)d_in[15], *b1 = (const float*)d_in[16];
    const float *W2  = (const float*)d_in[17], *b2 = (const float*)d_in[18];
    const float *W3  = (const float*)d_in[19], *b3 = (const float*)d_in[20];
    float* y = (float*)d_out;

    float *qemb, *gx, *t0, *g0, *m2, *bsum;
    unsigned* gsync;
    __half *ah, *al, *bh, *bl, *hsh, *hsl;
    cudaGetSymbolAddress((void**)&qemb, d_qemb);
    cudaGetSymbolAddress((void**)&gx,   d_gx);
    cudaGetSymbolAddress((void**)&t0,   d_t0);
    cudaGetSymbolAddress((void**)&g0,   d_g0);
    cudaGetSymbolAddress((void**)&m2,   d_m2);
    cudaGetSymbolAddress((void**)&bsum, d_bsum);
    cudaGetSymbolAddress((void**)&gsync, d_gsync);
    cudaGetSymbolAddress((void**)&ah,   d_ah);
    cudaGetSymbolAddress((void**)&al,   d_al);
    cudaGetSymbolAddress((void**)&bh,   d_bh);
    cudaGetSymbolAddress((void**)&bl,   d_bl);
    cudaGetSymbolAddress((void**)&hsh,  d_hsh);
    cudaGetSymbolAddress((void**)&hsl,  d_hsl);

    cudaFuncSetAttribute(mma_gemm, cudaFuncAttributeMaxDynamicSharedMemorySize, MMA_SMEM);
    cudaFuncSetAttribute(lstm_layer_mma, cudaFuncAttributeMaxDynamicSharedMemorySize, LSTM2_SMEM);

    const long NE = (long)LSEQ * BATCH * HID;

    // ---- prep ----
    bsum_k<<<(NLAY * G4H + 255) / 256, 256>>>(bih, bhh, bsum);
    embed_k<<<(unsigned)((NE + 255) / 256), 256>>>(q, c, r, qsh, csh, rsh,
                                                   Wq, Wc, Wr, hsh, hsl, qemb);
    cudaMemsetAsync(gsync, 0, 8, 0);

    // ---- 5-layer LSTM ----
    for (int l = 0; l < NLAY; l++) {
        split_k<<<(unsigned)((long)G4H * HID / 4 / 256), 256>>>(
            Wih + (size_t)l * G4H * HID, bh, bl, (long)G4H * HID);
        mma_gemm<<<dim3(G4H / 128, (LSEQ * BATCH) / 128), 256, MMA_SMEM>>>(
            hsh, hsl, bh, bl, gx, nullptr, nullptr, G4H, HID,
            bsum + (size_t)l * G4H, 0);
        lstm_layer_mma<<<128, 256, LSTM2_SMEM>>>(
            gx, Whh + (size_t)l * G4H * HID, hsh, hsl, (unsigned)(l * LSEQ));
    }

    // ---- 5 GCN layers (blend = hsh/hsl of last LSTM layer) ----
    splitT_k<<<dim3(16, 16), dim3(32, 32)>>>(Wg, bh, bl, HID, HID);
    mma_gemm<<<dim3(HID / 128, (LSEQ * BATCH) / 128), 256, MMA_SMEM>>>(
        hsh, hsl, bh, bl, t0, nullptr, nullptr, HID, HID, nullptr, 0);
    adj_gemm<<<dim3((BATCH * HID) / 1024, LSEQ / 25), 256>>>(
        adj, t0, nullptr, 1, hsh, hsl, ah, al);
    for (int i = 1; i < 5; i++) {
        splitT_k<<<dim3(16, 16), dim3(32, 32)>>>(Wg + (size_t)i * HID * HID, bh, bl,
                                                 HID, HID);
        mma_gemm<<<dim3(HID / 128, (LSEQ * BATCH) / 128), 256, MMA_SMEM>>>(
            ah, al, bh, bl, t0, nullptr, nullptr, HID, HID, nullptr, 0);
        if (i < 4) {
            adj_gemm<<<dim3((BATCH * HID) / 1024, LSEQ / 25), 256>>>(
                adj, t0, nullptr, 1, hsh, hsl, ah, al);
        } else {
            adj_gemm<<<dim3((BATCH * HID) / 1024, LSEQ / 25), 256>>>(
                adj, t0, g0, 0, nullptr, nullptr, nullptr, nullptr);
        }
    }

    // ---- concat + MLP head ----
    {
        const long n = (long)BATCH * SEQ * (2 * EMB);
        concat_half_k<<<(unsigned)((n + 255) / 256), 256>>>(g0, qemb, ah, al);
    }
    const int M = BATCH * SEQ;   // 50944 = 398*128
    splitT_k<<<dim3(16, 32), dim3(32, 32)>>>(W1, bh, bl, 2 * EMB, NFC1);
    mma_gemm<<<dim3(NFC1 / 128, M / 128), 256, MMA_SMEM>>>(
        ah, al, bh, bl, nullptr, hsh, hsl, NFC1, 2 * EMB, b1, 1);
    splitT_k<<<dim3(8, 16), dim3(32, 32)>>>(W2, bh, bl, NFC1, NFC2);
    mma_gemm<<<dim3(NFC2 / 128, M / 128), 256, MMA_SMEM>>>(
        hsh, hsl, bh, bl, m2, nullptr, nullptr, NFC2, NFC1, b2, 1);
    mlp3_k<<<(M * 32 + 255) / 256, 256>>>(m2, W3, b3, y, M);
}